// round 1
// baseline (speedup 1.0000x reference)
#include <cuda_runtime.h>

#define NT 6144
#define KIN 256
#define DM 128
#define NH 4
#define HD 32
#define NSLICE 4
#define SLICE_KEYS (NT / NSLICE)   // 1536
#define BN 128

// Scratch (device globals: allocation-free rule)
__device__ float g_q[NT * DM];
__device__ float g_k[NT * DM];
__device__ float g_v[NT * DM];
__device__ float g_attp[NSLICE][NT * DM];   // per-slice partial sum(p*v)
__device__ float g_lp[NSLICE][NT * NH];     // per-slice partial sum(p)

// ---------------------------------------------------------------------------
// GEMM: C[m, 0:128] = A[m, 0:K] @ B[K,128] + bias.
// BM=128 rows per block, BN=128 (full width), BK=16, 256 threads, 8x8 micro.
// NORM=true: A is the summed+normalized attention partials (output proj path).
// ---------------------------------------------------------------------------
template <int K, bool NORM>
__global__ __launch_bounds__(256) void gemm128(
    const float* __restrict__ A,
    const float* __restrict__ B0, const float* __restrict__ B1, const float* __restrict__ B2,
    const float* __restrict__ b0, const float* __restrict__ b1, const float* __restrict__ b2,
    float* __restrict__ out)
{
    const float* B    = (blockIdx.y == 0) ? B0 : (blockIdx.y == 1) ? B1 : B2;
    const float* bias = (blockIdx.y == 0) ? b0 : (blockIdx.y == 1) ? b1 : b2;
    float* C;
    if (NORM) C = out;
    else      C = (blockIdx.y == 0) ? g_q : (blockIdx.y == 1) ? g_k : g_v;

    __shared__ float As[16][128 + 4];
    __shared__ float Bs[16][128];

    const int tid = threadIdx.x;
    const int m0  = blockIdx.x * 128;
    const int tx  = tid & 15;
    const int ty  = tid >> 4;

    float acc[8][8];
#pragma unroll
    for (int i = 0; i < 8; ++i)
#pragma unroll
        for (int j = 0; j < 8; ++j) acc[i][j] = 0.f;

    for (int k0 = 0; k0 < K; k0 += 16) {
        // ---- load A tile (128 x 16), transposed into As[k][m] ----
#pragma unroll
        for (int r = 0; r < 2; ++r) {
            int idx = tid + r * 256;         // 0..511 float4 slots
            int m   = idx >> 2;              // 0..127
            int kq  = (idx & 3) << 2;        // 0,4,8,12
            float4 av;
            if (!NORM) {
                av = *(const float4*)&A[(size_t)(m0 + m) * K + k0 + kq];
            } else {
                // Sum partial slices and normalize by per-(row,head) l.
                int row = m0 + m;
                int kk  = k0 + kq;           // same head for all 4 lanes of float4
                int hh  = kk >> 5;
                av = make_float4(0.f, 0.f, 0.f, 0.f);
                float lsum = 0.f;
#pragma unroll
                for (int s = 0; s < NSLICE; ++s) {
                    float4 t = *(const float4*)&g_attp[s][row * DM + kk];
                    av.x += t.x; av.y += t.y; av.z += t.z; av.w += t.w;
                    lsum += g_lp[s][row * NH + hh];
                }
                float inv = 1.0f / lsum;
                av.x *= inv; av.y *= inv; av.z *= inv; av.w *= inv;
            }
            As[kq + 0][m] = av.x;
            As[kq + 1][m] = av.y;
            As[kq + 2][m] = av.z;
            As[kq + 3][m] = av.w;
        }
        // ---- load B tile (16 x 128) ----
#pragma unroll
        for (int r = 0; r < 2; ++r) {
            int idx = tid + r * 256;
            int kr  = idx >> 5;              // 0..15
            int nq  = (idx & 31) << 2;       // 0..124
            *(float4*)&Bs[kr][nq] = *(const float4*)&B[(size_t)(k0 + kr) * 128 + nq];
        }
        __syncthreads();

#pragma unroll
        for (int kk = 0; kk < 16; ++kk) {
            float a[8], b[8];
#pragma unroll
            for (int i = 0; i < 8; ++i) a[i] = As[kk][ty * 8 + i];
#pragma unroll
            for (int j = 0; j < 8; ++j) b[j] = Bs[kk][tx * 8 + j];
#pragma unroll
            for (int i = 0; i < 8; ++i)
#pragma unroll
                for (int j = 0; j < 8; ++j) acc[i][j] = fmaf(a[i], b[j], acc[i][j]);
        }
        __syncthreads();
    }

#pragma unroll
    for (int i = 0; i < 8; ++i) {
        int m = m0 + ty * 8 + i;
#pragma unroll
        for (int j = 0; j < 8; j += 4) {
            int n = tx * 8 + j;
            float4 o;
            o.x = acc[i][j + 0] + bias[n + 0];
            o.y = acc[i][j + 1] + bias[n + 1];
            o.z = acc[i][j + 2] + bias[n + 2];
            o.w = acc[i][j + 3] + bias[n + 3];
            *(float4*)&C[(size_t)m * 128 + n] = o;
        }
    }
}

// ---------------------------------------------------------------------------
// Fused attention (no-max-softmax, split-K over keys).
// Block: 128 threads = 128 query rows, one head, one key slice.
// Grid: (NT/128, NH, NSLICE).
// ---------------------------------------------------------------------------
__global__ __launch_bounds__(128) void attn_kernel(const float* __restrict__ dist_w)
{
    __shared__ float Ks[BN][HD];
    __shared__ float Vs[BN][HD];
    __shared__ float Aj[BN];

    const int tid = threadIdx.x;
    const int i   = blockIdx.x * 128 + tid;
    const int h   = blockIdx.y;
    const int sl  = blockIdx.z;

    const float dw    = dist_w[h];
    const float scale = 0.17677669529663687f;   // 1/sqrt(32)
    const float ai    = (float)i / 100.0f;

    float qr[HD];
    const float* qrow = &g_q[(size_t)i * DM + h * HD];
#pragma unroll
    for (int d = 0; d < HD; d += 4) {
        float4 t = *(const float4*)&qrow[d];
        qr[d] = t.x; qr[d + 1] = t.y; qr[d + 2] = t.z; qr[d + 3] = t.w;
    }

    float o[HD];
#pragma unroll
    for (int d = 0; d < HD; ++d) o[d] = 0.f;
    float l = 0.f;

    const int jbase = sl * SLICE_KEYS;
    for (int jt = 0; jt < SLICE_KEYS; jt += BN) {
        const int jb = jbase + jt;
        __syncthreads();   // previous tile fully consumed
        // load K/V tile: BN*HD floats each, as float4 (8 per thread per matrix)
#pragma unroll
        for (int r = 0; r < 8; ++r) {
            int idx = tid + r * 128;
            int j   = idx >> 3;
            int dq  = (idx & 7) << 2;
            *(float4*)&Ks[j][dq] = *(const float4*)&g_k[(size_t)(jb + j) * DM + h * HD + dq];
            *(float4*)&Vs[j][dq] = *(const float4*)&g_v[(size_t)(jb + j) * DM + h * HD + dq];
        }
        Aj[tid] = (float)(jb + tid) / 100.0f;
        __syncthreads();

#pragma unroll 2
        for (int jj = 0; jj < BN; ++jj) {
            float s0 = 0.f, s1 = 0.f, s2 = 0.f, s3 = 0.f;
            const float4* kp = (const float4*)&Ks[jj][0];
#pragma unroll
            for (int q = 0; q < 8; ++q) {
                float4 k4 = kp[q];
                s0 = fmaf(qr[q * 4 + 0], k4.x, s0);
                s1 = fmaf(qr[q * 4 + 1], k4.y, s1);
                s2 = fmaf(qr[q * 4 + 2], k4.z, s2);
                s3 = fmaf(qr[q * 4 + 3], k4.w, s3);
            }
            float s = ((s0 + s1) + (s2 + s3)) * scale - dw * fabsf(ai - Aj[jj]);
            float p = __expf(s);   // bounded above (~e^0.5): no max-subtraction needed
            l += p;
            const float4* vp = (const float4*)&Vs[jj][0];
#pragma unroll
            for (int q = 0; q < 8; ++q) {
                float4 v4 = vp[q];
                o[q * 4 + 0] = fmaf(p, v4.x, o[q * 4 + 0]);
                o[q * 4 + 1] = fmaf(p, v4.y, o[q * 4 + 1]);
                o[q * 4 + 2] = fmaf(p, v4.z, o[q * 4 + 2]);
                o[q * 4 + 3] = fmaf(p, v4.w, o[q * 4 + 3]);
            }
        }
    }

    g_lp[sl][i * NH + h] = l;
    float* op = &g_attp[sl][(size_t)i * DM + h * HD];
#pragma unroll
    for (int d = 0; d < HD; d += 4) {
        float4 t = make_float4(o[d], o[d + 1], o[d + 2], o[d + 3]);
        *(float4*)&op[d] = t;
    }
}

// ---------------------------------------------------------------------------
extern "C" void kernel_launch(void* const* d_in, const int* in_sizes, int n_in,
                              void* d_out, int out_size)
{
    const float* x  = (const float*)d_in[0];
    const float* Wq = (const float*)d_in[1];
    const float* bq = (const float*)d_in[2];
    const float* Wk = (const float*)d_in[3];
    const float* bk = (const float*)d_in[4];
    const float* Wv = (const float*)d_in[5];
    const float* bv = (const float*)d_in[6];
    const float* Wo = (const float*)d_in[7];
    const float* bo = (const float*)d_in[8];
    const float* dw = (const float*)d_in[9];
    float* out = (float*)d_out;

    // 1) QKV projections (blockIdx.y selects q/k/v)
    gemm128<KIN, false><<<dim3(NT / 128, 3, 1), 256>>>(x, Wq, Wk, Wv, bq, bk, bv, nullptr);
    // 2) Fused distance-biased attention, split 4x over keys
    attn_kernel<<<dim3(NT / 128, NH, NSLICE), 128>>>(dw);
    // 3) Output projection, with slice-combine + 1/l normalization folded into A load
    gemm128<DM, true><<<dim3(NT / 128, 1, 1), 256>>>(nullptr, Wo, Wo, Wo, bo, bo, bo, out);
}

// round 3
// speedup vs baseline: 6.6469x; 6.6469x over previous
#include <cuda_runtime.h>
#include <cuda_fp16.h>
#include <cstdint>

#define NT 6144
#define KIN 256
#define DM 128
#define NH 4
#define HD 32
#define NSLICE 3
#define SLICE_KEYS (NT / NSLICE)   // 2048
#define BM 64
#define BN 64
#define NKT (SLICE_KEYS / BN)      // 32 key tiles per block

// Scratch (device globals: allocation-free rule)
__device__ __half g_qh[NT * DM];
__device__ __half g_kh[NT * DM];
__device__ __half g_vh[NT * DM];
__device__ float g_attp[NSLICE][NT * DM];   // per-slice partial sum(p*v)
__device__ float g_lp[NSLICE][NT * NH];     // per-slice partial sum(p)

// ---------------------------------------------------------------------------
// PTX helpers
// ---------------------------------------------------------------------------
__device__ __forceinline__ float ex2f(float x) {
    float y; asm("ex2.approx.ftz.f32 %0, %1;" : "=f"(y) : "f"(x)); return y;
}
__device__ __forceinline__ uint32_t packh(float lo, float hi) {
    __half2 h = __floats2half2_rn(lo, hi);      // lo -> low 16 bits
    return *(uint32_t*)&h;
}
__device__ __forceinline__ void mma_f16(float d[4], uint32_t a0, uint32_t a1, uint32_t a2, uint32_t a3,
                                        uint32_t b0, uint32_t b1) {
    asm volatile(
        "mma.sync.aligned.m16n8k16.row.col.f32.f16.f16.f32 "
        "{%0,%1,%2,%3}, {%4,%5,%6,%7}, {%8,%9}, {%0,%1,%2,%3};\n"
        : "+f"(d[0]), "+f"(d[1]), "+f"(d[2]), "+f"(d[3])
        : "r"(a0), "r"(a1), "r"(a2), "r"(a3), "r"(b0), "r"(b1));
}
__device__ __forceinline__ void ldsm4(uint32_t r[4], uint32_t addr) {
    asm volatile("ldmatrix.sync.aligned.m8n8.x4.shared.b16 {%0,%1,%2,%3}, [%4];\n"
                 : "=r"(r[0]), "=r"(r[1]), "=r"(r[2]), "=r"(r[3]) : "r"(addr));
}
__device__ __forceinline__ void ldsm4t(uint32_t r[4], uint32_t addr) {
    asm volatile("ldmatrix.sync.aligned.m8n8.x4.trans.shared.b16 {%0,%1,%2,%3}, [%4];\n"
                 : "=r"(r[0]), "=r"(r[1]), "=r"(r[2]), "=r"(r[3]) : "r"(addr));
}
__device__ __forceinline__ void cpa16(uint32_t saddr, const void* gaddr) {
    asm volatile("cp.async.cg.shared.global [%0], [%1], 16;\n" :: "r"(saddr), "l"(gaddr));
}
__device__ __forceinline__ void cpa_commit() { asm volatile("cp.async.commit_group;\n" ::); }
__device__ __forceinline__ void cpa_wait1()  { asm volatile("cp.async.wait_group 1;\n" ::); }

// swizzled byte offset of 16B chunk (row, c) within a [rows][32 half] tile
#define SOFF(r, c) ((uint32_t)((((r) << 2) + ((c) ^ (((r) >> 1) & 3))) << 4))

// ---------------------------------------------------------------------------
// QKV projection GEMM: C[m,0:128] = x[m,0:256] @ W + b, output fp16.
// blockIdx.y selects q/k/v. 128 rows/block, 256 threads, 8x8 micro-tile.
// ---------------------------------------------------------------------------
__global__ __launch_bounds__(256) void gemm_qkv(
    const float* __restrict__ A,
    const float* __restrict__ B0, const float* __restrict__ B1, const float* __restrict__ B2,
    const float* __restrict__ b0, const float* __restrict__ b1, const float* __restrict__ b2)
{
    const float* B    = (blockIdx.y == 0) ? B0 : (blockIdx.y == 1) ? B1 : B2;
    const float* bias = (blockIdx.y == 0) ? b0 : (blockIdx.y == 1) ? b1 : b2;
    __half* C         = (blockIdx.y == 0) ? g_qh : (blockIdx.y == 1) ? g_kh : g_vh;

    __shared__ float As[16][128 + 4];
    __shared__ float Bs[16][128];

    const int tid = threadIdx.x;
    const int m0  = blockIdx.x * 128;
    const int tx  = tid & 15;
    const int ty  = tid >> 4;

    float acc[8][8];
#pragma unroll
    for (int i = 0; i < 8; ++i)
#pragma unroll
        for (int j = 0; j < 8; ++j) acc[i][j] = 0.f;

    for (int k0 = 0; k0 < KIN; k0 += 16) {
#pragma unroll
        for (int r = 0; r < 2; ++r) {
            int idx = tid + r * 256;
            int m   = idx >> 2;
            int kq  = (idx & 3) << 2;
            float4 av = *(const float4*)&A[(size_t)(m0 + m) * KIN + k0 + kq];
            As[kq + 0][m] = av.x; As[kq + 1][m] = av.y;
            As[kq + 2][m] = av.z; As[kq + 3][m] = av.w;
        }
#pragma unroll
        for (int r = 0; r < 2; ++r) {
            int idx = tid + r * 256;
            int kr  = idx >> 5;
            int nq  = (idx & 31) << 2;
            *(float4*)&Bs[kr][nq] = *(const float4*)&B[(size_t)(k0 + kr) * 128 + nq];
        }
        __syncthreads();
#pragma unroll
        for (int kk = 0; kk < 16; ++kk) {
            float a[8], b[8];
#pragma unroll
            for (int i = 0; i < 8; ++i) a[i] = As[kk][ty * 8 + i];
#pragma unroll
            for (int j = 0; j < 8; ++j) b[j] = Bs[kk][tx * 8 + j];
#pragma unroll
            for (int i = 0; i < 8; ++i)
#pragma unroll
                for (int j = 0; j < 8; ++j) acc[i][j] = fmaf(a[i], b[j], acc[i][j]);
        }
        __syncthreads();
    }

#pragma unroll
    for (int i = 0; i < 8; ++i) {
        int m = m0 + ty * 8 + i;
#pragma unroll
        for (int j = 0; j < 8; j += 2) {
            int n = tx * 8 + j;
            __half2 t2 = __floats2half2_rn(acc[i][j] + bias[n], acc[i][j + 1] + bias[n + 1]);
            *(__half2*)&C[(size_t)m * DM + n] = t2;
        }
    }
}

// ---------------------------------------------------------------------------
// Fused attention: fp16 tensor-core flash attention (no-max softmax, split-K).
// Block: 128 threads = 4 warps x 16 query rows = 64 rows, one head, one slice.
// Grid: (NT/64, NH, NSLICE).
// ---------------------------------------------------------------------------
__global__ __launch_bounds__(128, 4) void attn_kernel(const float* __restrict__ dist_w)
{
    __shared__ __align__(16) __half Qs[BM * HD];
    __shared__ __align__(16) __half Ks[2][BN * HD];
    __shared__ __align__(16) __half Vs[2][BN * HD];

    const int tid   = threadIdx.x;
    const int lane  = tid & 31;
    const int w     = tid >> 5;
    const int h     = blockIdx.y;
    const int sl    = blockIdx.z;
    const int qbase = blockIdx.x * BM;
    const int jbase = sl * SLICE_KEYS;

    const int mg = lane >> 2, mt = lane & 3;   // mma group / thread-in-group
    const int lg = lane >> 3, lr = lane & 7;   // ldmatrix group / row

    const uint32_t qs0 = (uint32_t)__cvta_generic_to_shared(Qs);
    const uint32_t ks0 = (uint32_t)__cvta_generic_to_shared(Ks);
    const uint32_t vs0 = (uint32_t)__cvta_generic_to_shared(Vs);
    const uint32_t KVB = BN * HD * 2;          // bytes per K/V buffer

    const float dw  = dist_w[h];
    const float C1  = 0.17677669529663687f * 1.44269504088896340f; // scale*log2e
    const float nC2 = -dw * 1.44269504088896340f;

    // precomputed per-lane ldmatrix offsets (within a tile buffer)
    uint32_t offK[4][2], offV[4][2], offQ[2];
#pragma unroll
    for (int p = 0; p < 4; ++p)
#pragma unroll
        for (int kk = 0; kk < 2; ++kk) {
            int rowk = 16 * p + ((lg >> 1) << 3) + lr;
            offK[p][kk] = SOFF(rowk, 2 * kk + (lg & 1));
            int rowv = 16 * p + ((lg & 1) << 3) + lr;     // p acts as kc for V
            offV[p][kk] = SOFF(rowv, 2 * kk + (lg >> 1)); // kk acts as dpair
        }
#pragma unroll
    for (int kk = 0; kk < 2; ++kk) {
        int rowq = w * 16 + ((lg & 1) << 3) + lr;
        offQ[kk] = SOFF(rowq, 2 * kk + (lg >> 1));
    }

    // ---- async loads: group0 = Q + tile0, group1 = tile1
    {
        const int id0 = tid, id1 = tid + 128;
        const int r0 = id0 >> 2, c0 = id0 & 3, r1 = id1 >> 2, c1 = id1 & 3;
        cpa16(qs0 + SOFF(r0, c0), &g_qh[(size_t)(qbase + r0) * DM + h * HD + c0 * 8]);
        cpa16(qs0 + SOFF(r1, c1), &g_qh[(size_t)(qbase + r1) * DM + h * HD + c1 * 8]);
        cpa16(ks0 + SOFF(r0, c0), &g_kh[(size_t)(jbase + r0) * DM + h * HD + c0 * 8]);
        cpa16(ks0 + SOFF(r1, c1), &g_kh[(size_t)(jbase + r1) * DM + h * HD + c1 * 8]);
        cpa16(vs0 + SOFF(r0, c0), &g_vh[(size_t)(jbase + r0) * DM + h * HD + c0 * 8]);
        cpa16(vs0 + SOFF(r1, c1), &g_vh[(size_t)(jbase + r1) * DM + h * HD + c1 * 8]);
        cpa_commit();
        const int jb1 = jbase + BN;
        cpa16(ks0 + KVB + SOFF(r0, c0), &g_kh[(size_t)(jb1 + r0) * DM + h * HD + c0 * 8]);
        cpa16(ks0 + KVB + SOFF(r1, c1), &g_kh[(size_t)(jb1 + r1) * DM + h * HD + c1 * 8]);
        cpa16(vs0 + KVB + SOFF(r0, c0), &g_vh[(size_t)(jb1 + r0) * DM + h * HD + c0 * 8]);
        cpa16(vs0 + KVB + SOFF(r1, c1), &g_vh[(size_t)(jb1 + r1) * DM + h * HD + c1 * 8]);
        cpa_commit();
    }
    cpa_wait1();
    __syncthreads();

    // Q fragments (held for the whole loop)
    uint32_t qf[2][4];
#pragma unroll
    for (int kk = 0; kk < 2; ++kk) ldsm4(qf[kk], qs0 + offQ[kk]);

    float O[4][4];
#pragma unroll
    for (int n = 0; n < 4; ++n)
#pragma unroll
        for (int r = 0; r < 4; ++r) O[n][r] = 0.f;
    float l0 = 0.f, l1 = 0.f;

    const float ai0 = (float)(qbase + w * 16 + mg) * 0.01f;
    const float ai1 = ai0 + 0.08f;

    for (int t = 0; t < NKT; ++t) {
        const int jb = jbase + t * BN;
        const uint32_t kb = ks0 + (uint32_t)(t & 1) * KVB;
        const uint32_t vb = vs0 + (uint32_t)(t & 1) * KVB;

        // ---- S = Q @ K^T
        float S[8][4];
#pragma unroll
        for (int c = 0; c < 8; ++c)
#pragma unroll
            for (int r = 0; r < 4; ++r) S[c][r] = 0.f;

        uint32_t kf[4][2][4];
#pragma unroll
        for (int p = 0; p < 4; ++p)
#pragma unroll
            for (int kk = 0; kk < 2; ++kk) ldsm4(kf[p][kk], kb + offK[p][kk]);
#pragma unroll
        for (int p = 0; p < 4; ++p)
#pragma unroll
            for (int s2 = 0; s2 < 2; ++s2)
#pragma unroll
                for (int kk = 0; kk < 2; ++kk)
                    mma_f16(S[2 * p + s2], qf[kk][0], qf[kk][1], qf[kk][2], qf[kk][3],
                            kf[p][kk][2 * s2], kf[p][kk][2 * s2 + 1]);

        // ---- softmax numerator: p = exp2(S*C1 - dw*log2e*|ai-aj|)
        uint32_t pp[8][2];
        const float ajt = (float)(jb + 2 * mt) * 0.01f;
#pragma unroll
        for (int c = 0; c < 8; ++c) {
            float ajA = ajt + (float)c * 0.08f;
            float ajB = ajA + 0.01f;
            float p00 = ex2f(fmaf(S[c][0], C1, nC2 * fabsf(ai0 - ajA)));
            float p01 = ex2f(fmaf(S[c][1], C1, nC2 * fabsf(ai0 - ajB)));
            float p10 = ex2f(fmaf(S[c][2], C1, nC2 * fabsf(ai1 - ajA)));
            float p11 = ex2f(fmaf(S[c][3], C1, nC2 * fabsf(ai1 - ajB)));
            l0 += p00 + p01;
            l1 += p10 + p11;
            pp[c][0] = packh(p00, p01);
            pp[c][1] = packh(p10, p11);
        }

        // ---- O += P @ V   (V fragments via ldmatrix.trans: no transpose copy)
        uint32_t vf[4][2][4];
#pragma unroll
        for (int kc = 0; kc < 4; ++kc)
#pragma unroll
            for (int dp = 0; dp < 2; ++dp) ldsm4t(vf[kc][dp], vb + offV[kc][dp]);
#pragma unroll
        for (int kc = 0; kc < 4; ++kc)
#pragma unroll
            for (int nt = 0; nt < 4; ++nt)
                mma_f16(O[nt], pp[2 * kc][0], pp[2 * kc][1], pp[2 * kc + 1][0], pp[2 * kc + 1][1],
                        vf[kc][nt >> 1][2 * (nt & 1)], vf[kc][nt >> 1][2 * (nt & 1) + 1]);

        __syncthreads();   // all warps done with buffer (t&1) before refill

        // ---- prefetch tile t+2 into buffer (t&1)
        if (t + 2 < NKT) {
            const int jb2 = jbase + (t + 2) * BN;
            const uint32_t kb2 = ks0 + (uint32_t)(t & 1) * KVB;
            const uint32_t vb2 = vs0 + (uint32_t)(t & 1) * KVB;
            const int id0 = tid, id1 = tid + 128;
            const int r0 = id0 >> 2, c0 = id0 & 3, r1 = id1 >> 2, c1 = id1 & 3;
            cpa16(kb2 + SOFF(r0, c0), &g_kh[(size_t)(jb2 + r0) * DM + h * HD + c0 * 8]);
            cpa16(kb2 + SOFF(r1, c1), &g_kh[(size_t)(jb2 + r1) * DM + h * HD + c1 * 8]);
            cpa16(vb2 + SOFF(r0, c0), &g_vh[(size_t)(jb2 + r0) * DM + h * HD + c0 * 8]);
            cpa16(vb2 + SOFF(r1, c1), &g_vh[(size_t)(jb2 + r1) * DM + h * HD + c1 * 8]);
        }
        cpa_commit();
        if (t < NKT - 1) {
            cpa_wait1();
            __syncthreads();   // next buffer ready & visible
        }
    }

    // ---- epilogue: l reduce over quad, write partials
    l0 += __shfl_xor_sync(0xffffffffu, l0, 1);
    l0 += __shfl_xor_sync(0xffffffffu, l0, 2);
    l1 += __shfl_xor_sync(0xffffffffu, l1, 1);
    l1 += __shfl_xor_sync(0xffffffffu, l1, 2);

    const int i0 = qbase + w * 16 + mg;
    const int i1 = i0 + 8;
    if (mt == 0) {
        g_lp[sl][i0 * NH + h] = l0;
        g_lp[sl][i1 * NH + h] = l1;
    }
    float* oB = &g_attp[sl][0];
#pragma unroll
    for (int nt = 0; nt < 4; ++nt) {
        int d = nt * 8 + 2 * mt;
        *(float2*)&oB[(size_t)i0 * DM + h * HD + d] = make_float2(O[nt][0], O[nt][1]);
        *(float2*)&oB[(size_t)i1 * DM + h * HD + d] = make_float2(O[nt][2], O[nt][3]);
    }
}

// ---------------------------------------------------------------------------
// Output projection: out = (sum_s attp / sum_s l) @ Wo + bo   (fp32)
// ---------------------------------------------------------------------------
__global__ __launch_bounds__(256) void gemm_out(
    const float* __restrict__ B, const float* __restrict__ bias, float* __restrict__ out)
{
    __shared__ float As[16][128 + 4];
    __shared__ float Bs[16][128];

    const int tid = threadIdx.x;
    const int m0  = blockIdx.x * 128;
    const int tx  = tid & 15;
    const int ty  = tid >> 4;

    float acc[8][8];
#pragma unroll
    for (int i = 0; i < 8; ++i)
#pragma unroll
        for (int j = 0; j < 8; ++j) acc[i][j] = 0.f;

    for (int k0 = 0; k0 < DM; k0 += 16) {
#pragma unroll
        for (int r = 0; r < 2; ++r) {
            int idx = tid + r * 256;
            int m   = idx >> 2;
            int kq  = (idx & 3) << 2;
            int row = m0 + m;
            int kk  = k0 + kq;
            int hh  = kk >> 5;
            float4 av = make_float4(0.f, 0.f, 0.f, 0.f);
            float lsum = 0.f;
#pragma unroll
            for (int s = 0; s < NSLICE; ++s) {
                float4 tv = *(const float4*)&g_attp[s][(size_t)row * DM + kk];
                av.x += tv.x; av.y += tv.y; av.z += tv.z; av.w += tv.w;
                lsum += g_lp[s][row * NH + hh];
            }
            float inv = 1.0f / lsum;
            As[kq + 0][m] = av.x * inv; As[kq + 1][m] = av.y * inv;
            As[kq + 2][m] = av.z * inv; As[kq + 3][m] = av.w * inv;
        }
#pragma unroll
        for (int r = 0; r < 2; ++r) {
            int idx = tid + r * 256;
            int kr  = idx >> 5;
            int nq  = (idx & 31) << 2;
            *(float4*)&Bs[kr][nq] = *(const float4*)&B[(size_t)(k0 + kr) * 128 + nq];
        }
        __syncthreads();
#pragma unroll
        for (int kk = 0; kk < 16; ++kk) {
            float a[8], b[8];
#pragma unroll
            for (int i = 0; i < 8; ++i) a[i] = As[kk][ty * 8 + i];
#pragma unroll
            for (int j = 0; j < 8; ++j) b[j] = Bs[kk][tx * 8 + j];
#pragma unroll
            for (int i = 0; i < 8; ++i)
#pragma unroll
                for (int j = 0; j < 8; ++j) acc[i][j] = fmaf(a[i], b[j], acc[i][j]);
        }
        __syncthreads();
    }

#pragma unroll
    for (int i = 0; i < 8; ++i) {
        int m = m0 + ty * 8 + i;
#pragma unroll
        for (int j = 0; j < 8; j += 4) {
            int n = tx * 8 + j;
            float4 o;
            o.x = acc[i][j + 0] + bias[n + 0];
            o.y = acc[i][j + 1] + bias[n + 1];
            o.z = acc[i][j + 2] + bias[n + 2];
            o.w = acc[i][j + 3] + bias[n + 3];
            *(float4*)&out[(size_t)m * 128 + n] = o;
        }
    }
}

// ---------------------------------------------------------------------------
extern "C" void kernel_launch(void* const* d_in, const int* in_sizes, int n_in,
                              void* d_out, int out_size)
{
    const float* x  = (const float*)d_in[0];
    const float* Wq = (const float*)d_in[1];
    const float* bq = (const float*)d_in[2];
    const float* Wk = (const float*)d_in[3];
    const float* bk = (const float*)d_in[4];
    const float* Wv = (const float*)d_in[5];
    const float* bv = (const float*)d_in[6];
    const float* Wo = (const float*)d_in[7];
    const float* bo = (const float*)d_in[8];
    const float* dw = (const float*)d_in[9];
    float* out = (float*)d_out;

    gemm_qkv<<<dim3(NT / 128, 3, 1), 256>>>(x, Wq, Wk, Wv, bq, bk, bv);
    attn_kernel<<<dim3(NT / BM, NH, NSLICE), 128>>>(dw);
    gemm_out<<<dim3(NT / 128, 1, 1), 256>>>(Wo, bo, out);
}

// round 4
// speedup vs baseline: 7.9053x; 1.1893x over previous
#include <cuda_runtime.h>
#include <cuda_fp16.h>
#include <cstdint>

#define NT 6144
#define KIN 256
#define DM 128
#define NH 4
#define HD 32
#define NSLICE 3
#define SLICE_KEYS (NT / NSLICE)   // 2048
#define BM 64
#define BN 64
#define NKT (SLICE_KEYS / BN)      // 32 key tiles per block

#define C1F 0.25502050681732154f   // (1/sqrt(32)) * log2(e)

// Scratch (device globals: allocation-free rule)
__device__ __half g_xh[NT * KIN];
__device__ __half g_wht[3 * KIN * DM];      // transposed [w][n][k], Wq pre-scaled by C1F
__device__ __half g_qh[NT * DM];
__device__ __half g_kh[NT * DM];
__device__ __half g_vh[NT * DM];
__device__ float g_attp[NSLICE][NT * DM];   // per-slice partial sum(p*v)
__device__ float g_lp[NSLICE][NT * NH];     // per-slice partial sum(p)

// ---------------------------------------------------------------------------
// PTX helpers
// ---------------------------------------------------------------------------
__device__ __forceinline__ uint32_t pack_f16x2(float lo, float hi) {
    uint32_t r; asm("cvt.rn.f16x2.f32 %0, %1, %2;" : "=r"(r) : "f"(hi), "f"(lo)); return r;
}
__device__ __forceinline__ uint32_t ex2_h2(uint32_t a) {
    uint32_t r; asm("ex2.approx.f16x2 %0, %1;" : "=r"(r) : "r"(a)); return r;
}
__device__ __forceinline__ void mma_f16(float d[4], uint32_t a0, uint32_t a1, uint32_t a2, uint32_t a3,
                                        uint32_t b0, uint32_t b1) {
    asm volatile(
        "mma.sync.aligned.m16n8k16.row.col.f32.f16.f16.f32 "
        "{%0,%1,%2,%3}, {%4,%5,%6,%7}, {%8,%9}, {%0,%1,%2,%3};\n"
        : "+f"(d[0]), "+f"(d[1]), "+f"(d[2]), "+f"(d[3])
        : "r"(a0), "r"(a1), "r"(a2), "r"(a3), "r"(b0), "r"(b1));
}
__device__ __forceinline__ void ldsm4(uint32_t r[4], uint32_t addr) {
    asm volatile("ldmatrix.sync.aligned.m8n8.x4.shared.b16 {%0,%1,%2,%3}, [%4];\n"
                 : "=r"(r[0]), "=r"(r[1]), "=r"(r[2]), "=r"(r[3]) : "r"(addr));
}
__device__ __forceinline__ void ldsm4t(uint32_t r[4], uint32_t addr) {
    asm volatile("ldmatrix.sync.aligned.m8n8.x4.trans.shared.b16 {%0,%1,%2,%3}, [%4];\n"
                 : "=r"(r[0]), "=r"(r[1]), "=r"(r[2]), "=r"(r[3]) : "r"(addr));
}
__device__ __forceinline__ void cpa16(uint32_t saddr, const void* gaddr) {
    asm volatile("cp.async.cg.shared.global [%0], [%1], 16;\n" :: "r"(saddr), "l"(gaddr));
}
__device__ __forceinline__ void cpa_commit() { asm volatile("cp.async.commit_group;\n" ::); }
__device__ __forceinline__ void cpa_wait1()  { asm volatile("cp.async.wait_group 1;\n" ::); }

// swizzled byte offset of 16B chunk (row, c) within a [rows][32 half] tile
#define SOFF(r, c) ((uint32_t)((((r) << 2) + ((c) ^ (((r) >> 1) & 3))) << 4))

// ---------------------------------------------------------------------------
// Conversion kernel: x -> fp16 (g_xh); W -> fp16 transposed [n][k] (g_wht).
// Wq (and bq, later in gemm epilogue) folded with C1F = scale*log2e.
// ---------------------------------------------------------------------------
__global__ __launch_bounds__(256) void convert_kernel(
    const float* __restrict__ x,
    const float* __restrict__ Wq, const float* __restrict__ Wk, const float* __restrict__ Wv)
{
    const int b = blockIdx.x, tid = threadIdx.x;
    if (b < 1536) {
        int base = b * 1024 + tid * 4;
        float4 v = *(const float4*)&x[base];
        *(__half2*)&g_xh[base]     = __floats2half2_rn(v.x, v.y);
        *(__half2*)&g_xh[base + 2] = __floats2half2_rn(v.z, v.w);
    } else {
        int bb = b - 1536;              // 0..47
        int w = bb >> 4, part = bb & 15;
        const float* W = (w == 0) ? Wq : (w == 1) ? Wk : Wv;
        float scale = (w == 0) ? C1F : 1.0f;
        __half* dst = g_wht + (size_t)w * (KIN * DM);
#pragma unroll
        for (int i = tid; i < 16 * DM; i += 256) {
            int k = part * 16 + (i >> 7);
            int n = i & 127;
            dst[n * KIN + k] = __float2half(W[k * DM + n] * scale);
        }
    }
}

// ---------------------------------------------------------------------------
// QKV projection GEMM (fp16 tensor cores): C = x @ W + b, output fp16.
// A = x [m][k] (ldsm4, like Q), B = W^T [n][k] (ldsm4, like K).
// Block: 256 threads = 8 warps; M=128, N=128, K=256 (8 stages of BK=32).
// ---------------------------------------------------------------------------
__global__ __launch_bounds__(256, 2) void gemm_qkv_tc(
    const float* __restrict__ bq, const float* __restrict__ bk, const float* __restrict__ bv)
{
    __shared__ __align__(16) __half Xs[2][128 * 32];
    __shared__ __align__(16) __half Ws[2][128 * 32];

    const int tid = threadIdx.x, lane = tid & 31, w = tid >> 5;
    const int y = blockIdx.y;
    const int m0 = blockIdx.x * 128;
    const __half* wht = g_wht + (size_t)y * (KIN * DM);
    const float* bias = (y == 0) ? bq : (y == 1) ? bk : bv;
    const float bscale = (y == 0) ? C1F : 1.0f;
    __half* C = (y == 0) ? g_qh : (y == 1) ? g_kh : g_vh;

    const int lg = lane >> 3, lr = lane & 7;
    const int mg = lane >> 2, mt = lane & 3;

    const uint32_t xs0 = (uint32_t)__cvta_generic_to_shared(Xs);
    const uint32_t ws0 = (uint32_t)__cvta_generic_to_shared(Ws);
    const uint32_t BUF = 128 * 32 * 2;   // bytes per buffer

    // prologue: stages 0, 1
#pragma unroll
    for (int s = 0; s < 2; ++s) {
#pragma unroll
        for (int r = 0; r < 2; ++r) {
            int id = tid + r * 256;
            int row = id >> 2, c = id & 3;
            cpa16(xs0 + s * BUF + SOFF(row, c), &g_xh[(size_t)(m0 + row) * KIN + s * 32 + c * 8]);
            cpa16(ws0 + s * BUF + SOFF(row, c), &wht[(size_t)row * KIN + s * 32 + c * 8]);
        }
        cpa_commit();
    }

    float Cf[16][4];
#pragma unroll
    for (int f = 0; f < 16; ++f)
#pragma unroll
        for (int r = 0; r < 4; ++r) Cf[f][r] = 0.f;

    uint32_t offA[2], offB[8][2];
#pragma unroll
    for (int kk = 0; kk < 2; ++kk)
        offA[kk] = SOFF(w * 16 + ((lg & 1) << 3) + lr, 2 * kk + (lg >> 1));
#pragma unroll
    for (int g = 0; g < 8; ++g)
#pragma unroll
        for (int kk = 0; kk < 2; ++kk)
            offB[g][kk] = SOFF(g * 16 + ((lg >> 1) << 3) + lr, 2 * kk + (lg & 1));

    for (int s = 0; s < 8; ++s) {
        cpa_wait1();
        __syncthreads();
        const uint32_t xb = xs0 + (uint32_t)(s & 1) * BUF;
        const uint32_t wb = ws0 + (uint32_t)(s & 1) * BUF;
#pragma unroll
        for (int kk = 0; kk < 2; ++kk) {
            uint32_t af[4];
            ldsm4(af, xb + offA[kk]);
#pragma unroll
            for (int g = 0; g < 8; ++g) {
                uint32_t bf[4];
                ldsm4(bf, wb + offB[g][kk]);
                mma_f16(Cf[2 * g],     af[0], af[1], af[2], af[3], bf[0], bf[1]);
                mma_f16(Cf[2 * g + 1], af[0], af[1], af[2], af[3], bf[2], bf[3]);
            }
        }
        __syncthreads();
        if (s + 2 < 8) {
            int k0 = (s + 2) * 32;
#pragma unroll
            for (int r = 0; r < 2; ++r) {
                int id = tid + r * 256;
                int row = id >> 2, c = id & 3;
                cpa16(xb + SOFF(row, c), &g_xh[(size_t)(m0 + row) * KIN + k0 + c * 8]);
                cpa16(wb + SOFF(row, c), &wht[(size_t)row * KIN + k0 + c * 8]);
            }
        }
        cpa_commit();
    }

    // epilogue: add bias, convert to fp16
    const int mr0 = m0 + w * 16 + mg;
    const int mr1 = mr0 + 8;
#pragma unroll
    for (int g = 0; g < 8; ++g)
#pragma unroll
        for (int s2 = 0; s2 < 2; ++s2) {
            int n = g * 16 + s2 * 8 + 2 * mt;
            float b0 = bias[n] * bscale, b1 = bias[n + 1] * bscale;
            float* d = Cf[2 * g + s2];
            *(__half2*)&C[(size_t)mr0 * DM + n] = __floats2half2_rn(d[0] + b0, d[1] + b1);
            *(__half2*)&C[(size_t)mr1 * DM + n] = __floats2half2_rn(d[2] + b0, d[3] + b1);
        }
}

// ---------------------------------------------------------------------------
// Fused attention: fp16 tensor-core flash attention (no-max softmax, split-K).
// Q pre-scaled by C1F, so p = ex2(S + nC2*|ai-aj|). exp via ex2.approx.f16x2
// (2 exps/MUFU op, output IS the fp16 P fragment). l = P @ ones via mma.
// ---------------------------------------------------------------------------
__global__ __launch_bounds__(128, 4) void attn_kernel(const float* __restrict__ dist_w)
{
    __shared__ __align__(16) __half Qs[BM * HD];
    __shared__ __align__(16) __half Ks[2][BN * HD];
    __shared__ __align__(16) __half Vs[2][BN * HD];

    const int tid   = threadIdx.x;
    const int lane  = tid & 31;
    const int w     = tid >> 5;
    const int h     = blockIdx.y;
    const int sl    = blockIdx.z;
    const int qbase = blockIdx.x * BM;
    const int jbase = sl * SLICE_KEYS;

    const int mg = lane >> 2, mt = lane & 3;
    const int lg = lane >> 3, lr = lane & 7;

    const uint32_t qs0 = (uint32_t)__cvta_generic_to_shared(Qs);
    const uint32_t ks0 = (uint32_t)__cvta_generic_to_shared(Ks);
    const uint32_t vs0 = (uint32_t)__cvta_generic_to_shared(Vs);
    const uint32_t KVB = BN * HD * 2;

    const float nC2 = -dist_w[h] * 1.44269504088896340f;

    uint32_t offK[4][2], offV[4][2], offQ[2];
#pragma unroll
    for (int p = 0; p < 4; ++p)
#pragma unroll
        for (int kk = 0; kk < 2; ++kk) {
            int rowk = 16 * p + ((lg >> 1) << 3) + lr;
            offK[p][kk] = SOFF(rowk, 2 * kk + (lg & 1));
            int rowv = 16 * p + ((lg & 1) << 3) + lr;
            offV[p][kk] = SOFF(rowv, 2 * kk + (lg >> 1));
        }
#pragma unroll
    for (int kk = 0; kk < 2; ++kk) {
        int rowq = w * 16 + ((lg & 1) << 3) + lr;
        offQ[kk] = SOFF(rowq, 2 * kk + (lg >> 1));
    }

    // async loads: group0 = Q + tile0, group1 = tile1
    {
        const int id0 = tid, id1 = tid + 128;
        const int r0 = id0 >> 2, c0 = id0 & 3, r1 = id1 >> 2, c1 = id1 & 3;
        cpa16(qs0 + SOFF(r0, c0), &g_qh[(size_t)(qbase + r0) * DM + h * HD + c0 * 8]);
        cpa16(qs0 + SOFF(r1, c1), &g_qh[(size_t)(qbase + r1) * DM + h * HD + c1 * 8]);
        cpa16(ks0 + SOFF(r0, c0), &g_kh[(size_t)(jbase + r0) * DM + h * HD + c0 * 8]);
        cpa16(ks0 + SOFF(r1, c1), &g_kh[(size_t)(jbase + r1) * DM + h * HD + c1 * 8]);
        cpa16(vs0 + SOFF(r0, c0), &g_vh[(size_t)(jbase + r0) * DM + h * HD + c0 * 8]);
        cpa16(vs0 + SOFF(r1, c1), &g_vh[(size_t)(jbase + r1) * DM + h * HD + c1 * 8]);
        cpa_commit();
        const int jb1 = jbase + BN;
        cpa16(ks0 + KVB + SOFF(r0, c0), &g_kh[(size_t)(jb1 + r0) * DM + h * HD + c0 * 8]);
        cpa16(ks0 + KVB + SOFF(r1, c1), &g_kh[(size_t)(jb1 + r1) * DM + h * HD + c1 * 8]);
        cpa16(vs0 + KVB + SOFF(r0, c0), &g_vh[(size_t)(jb1 + r0) * DM + h * HD + c0 * 8]);
        cpa16(vs0 + KVB + SOFF(r1, c1), &g_vh[(size_t)(jb1 + r1) * DM + h * HD + c1 * 8]);
        cpa_commit();
    }
    cpa_wait1();
    __syncthreads();

    uint32_t qf[2][4];
#pragma unroll
    for (int kk = 0; kk < 2; ++kk) ldsm4(qf[kk], qs0 + offQ[kk]);

    float O[4][4];
#pragma unroll
    for (int n = 0; n < 4; ++n)
#pragma unroll
        for (int r = 0; r < 4; ++r) O[n][r] = 0.f;
    float lC[4] = {0.f, 0.f, 0.f, 0.f};
    const uint32_t ONE2 = 0x3C003C00u;   // (fp16 1.0, fp16 1.0)

    const float ai0   = (float)(qbase + w * 16 + mg) * 0.01f;
    const float dbase = ai0 - (float)(jbase + 2 * mt) * 0.01f;

    for (int t = 0; t < NKT; ++t) {
        const uint32_t kb = ks0 + (uint32_t)(t & 1) * KVB;
        const uint32_t vb = vs0 + (uint32_t)(t & 1) * KVB;

        // ---- S = Q @ K^T (pre-scaled)
        float S[8][4];
#pragma unroll
        for (int c = 0; c < 8; ++c)
#pragma unroll
            for (int r = 0; r < 4; ++r) S[c][r] = 0.f;

        uint32_t kf[4][2][4];
#pragma unroll
        for (int p = 0; p < 4; ++p)
#pragma unroll
            for (int kk = 0; kk < 2; ++kk) ldsm4(kf[p][kk], kb + offK[p][kk]);
#pragma unroll
        for (int p = 0; p < 4; ++p)
#pragma unroll
            for (int s2 = 0; s2 < 2; ++s2)
#pragma unroll
                for (int kk = 0; kk < 2; ++kk)
                    mma_f16(S[2 * p + s2], qf[kk][0], qf[kk][1], qf[kk][2], qf[kk][3],
                            kf[p][kk][2 * s2], kf[p][kk][2 * s2 + 1]);

        // ---- p = ex2(S + nC2*|ai-aj|), two at a time on MUFU; output = P frag
        uint32_t pp[8][2];
        const float dt = dbase - (float)t * 0.64f;   // key base advances 64/tile
#pragma unroll
        for (int c = 0; c < 8; ++c) {
            float d00 = dt - 0.08f * (float)c;
            float d01 = d00 - 0.01f;
            float d10 = d00 + 0.08f;
            float d11 = d00 + 0.07f;
            float a00 = fmaf(nC2, fabsf(d00), S[c][0]);
            float a01 = fmaf(nC2, fabsf(d01), S[c][1]);
            float a10 = fmaf(nC2, fabsf(d10), S[c][2]);
            float a11 = fmaf(nC2, fabsf(d11), S[c][3]);
            pp[c][0] = ex2_h2(pack_f16x2(a00, a01));
            pp[c][1] = ex2_h2(pack_f16x2(a10, a11));
        }

        // ---- l += P @ ones (tensor core; all threads in row group get l)
#pragma unroll
        for (int kc = 0; kc < 4; ++kc)
            mma_f16(lC, pp[2 * kc][0], pp[2 * kc][1], pp[2 * kc + 1][0], pp[2 * kc + 1][1],
                    ONE2, ONE2);

        // ---- O += P @ V
        uint32_t vf[4][2][4];
#pragma unroll
        for (int kc = 0; kc < 4; ++kc)
#pragma unroll
            for (int dp = 0; dp < 2; ++dp) ldsm4t(vf[kc][dp], vb + offV[kc][dp]);
#pragma unroll
        for (int kc = 0; kc < 4; ++kc)
#pragma unroll
            for (int nt = 0; nt < 4; ++nt)
                mma_f16(O[nt], pp[2 * kc][0], pp[2 * kc][1], pp[2 * kc + 1][0], pp[2 * kc + 1][1],
                        vf[kc][nt >> 1][2 * (nt & 1)], vf[kc][nt >> 1][2 * (nt & 1) + 1]);

        __syncthreads();

        if (t + 2 < NKT) {
            const int jb2 = jbase + (t + 2) * BN;
            const uint32_t kb2 = ks0 + (uint32_t)(t & 1) * KVB;
            const uint32_t vb2 = vs0 + (uint32_t)(t & 1) * KVB;
            const int id0 = tid, id1 = tid + 128;
            const int r0 = id0 >> 2, c0 = id0 & 3, r1 = id1 >> 2, c1 = id1 & 3;
            cpa16(kb2 + SOFF(r0, c0), &g_kh[(size_t)(jb2 + r0) * DM + h * HD + c0 * 8]);
            cpa16(kb2 + SOFF(r1, c1), &g_kh[(size_t)(jb2 + r1) * DM + h * HD + c1 * 8]);
            cpa16(vb2 + SOFF(r0, c0), &g_vh[(size_t)(jb2 + r0) * DM + h * HD + c0 * 8]);
            cpa16(vb2 + SOFF(r1, c1), &g_vh[(size_t)(jb2 + r1) * DM + h * HD + c1 * 8]);
        }
        cpa_commit();
        if (t < NKT - 1) {
            cpa_wait1();
            __syncthreads();
        }
    }

    // ---- epilogue: write partials (lC already whole-row sums; no shuffles)
    const int i0 = qbase + w * 16 + mg;
    const int i1 = i0 + 8;
    if (mt == 0) {
        g_lp[sl][i0 * NH + h] = lC[0];
        g_lp[sl][i1 * NH + h] = lC[2];
    }
    float* oB = &g_attp[sl][0];
#pragma unroll
    for (int nt = 0; nt < 4; ++nt) {
        int d = nt * 8 + 2 * mt;
        *(float2*)&oB[(size_t)i0 * DM + h * HD + d] = make_float2(O[nt][0], O[nt][1]);
        *(float2*)&oB[(size_t)i1 * DM + h * HD + d] = make_float2(O[nt][2], O[nt][3]);
    }
}

// ---------------------------------------------------------------------------
// Output projection: out = (sum_s attp / sum_s l) @ Wo + bo   (fp32)
// ---------------------------------------------------------------------------
__global__ __launch_bounds__(256) void gemm_out(
    const float* __restrict__ B, const float* __restrict__ bias, float* __restrict__ out)
{
    __shared__ float As[16][128 + 4];
    __shared__ float Bs[16][128];

    const int tid = threadIdx.x;
    const int m0  = blockIdx.x * 128;
    const int tx  = tid & 15;
    const int ty  = tid >> 4;

    float acc[8][8];
#pragma unroll
    for (int i = 0; i < 8; ++i)
#pragma unroll
        for (int j = 0; j < 8; ++j) acc[i][j] = 0.f;

    for (int k0 = 0; k0 < DM; k0 += 16) {
#pragma unroll
        for (int r = 0; r < 2; ++r) {
            int idx = tid + r * 256;
            int m   = idx >> 2;
            int kq  = (idx & 3) << 2;
            int row = m0 + m;
            int kk  = k0 + kq;
            int hh  = kk >> 5;
            float4 av = make_float4(0.f, 0.f, 0.f, 0.f);
            float lsum = 0.f;
#pragma unroll
            for (int s = 0; s < NSLICE; ++s) {
                float4 tv = *(const float4*)&g_attp[s][(size_t)row * DM + kk];
                av.x += tv.x; av.y += tv.y; av.z += tv.z; av.w += tv.w;
                lsum += g_lp[s][row * NH + hh];
            }
            float inv = 1.0f / lsum;
            As[kq + 0][m] = av.x * inv; As[kq + 1][m] = av.y * inv;
            As[kq + 2][m] = av.z * inv; As[kq + 3][m] = av.w * inv;
        }
#pragma unroll
        for (int r = 0; r < 2; ++r) {
            int idx = tid + r * 256;
            int kr  = idx >> 5;
            int nq  = (idx & 31) << 2;
            *(float4*)&Bs[kr][nq] = *(const float4*)&B[(size_t)(k0 + kr) * 128 + nq];
        }
        __syncthreads();
#pragma unroll
        for (int kk = 0; kk < 16; ++kk) {
            float a[8], b[8];
#pragma unroll
            for (int i = 0; i < 8; ++i) a[i] = As[kk][ty * 8 + i];
#pragma unroll
            for (int j = 0; j < 8; ++j) b[j] = Bs[kk][tx * 8 + j];
#pragma unroll
            for (int i = 0; i < 8; ++i)
#pragma unroll
                for (int j = 0; j < 8; ++j) acc[i][j] = fmaf(a[i], b[j], acc[i][j]);
        }
        __syncthreads();
    }

#pragma unroll
    for (int i = 0; i < 8; ++i) {
        int m = m0 + ty * 8 + i;
#pragma unroll
        for (int j = 0; j < 8; j += 4) {
            int n = tx * 8 + j;
            float4 o;
            o.x = acc[i][j + 0] + bias[n + 0];
            o.y = acc[i][j + 1] + bias[n + 1];
            o.z = acc[i][j + 2] + bias[n + 2];
            o.w = acc[i][j + 3] + bias[n + 3];
            *(float4*)&out[(size_t)m * 128 + n] = o;
        }
    }
}

// ---------------------------------------------------------------------------
extern "C" void kernel_launch(void* const* d_in, const int* in_sizes, int n_in,
                              void* d_out, int out_size)
{
    const float* x  = (const float*)d_in[0];
    const float* Wq = (const float*)d_in[1];
    const float* bq = (const float*)d_in[2];
    const float* Wk = (const float*)d_in[3];
    const float* bk = (const float*)d_in[4];
    const float* Wv = (const float*)d_in[5];
    const float* bv = (const float*)d_in[6];
    const float* Wo = (const float*)d_in[7];
    const float* bo = (const float*)d_in[8];
    const float* dw = (const float*)d_in[9];
    float* out = (float*)d_out;

    convert_kernel<<<1584, 256>>>(x, Wq, Wk, Wv);
    gemm_qkv_tc<<<dim3(NT / 128, 3, 1), 256>>>(bq, bk, bv);
    attn_kernel<<<dim3(NT / BM, NH, NSLICE), 128>>>(dw);
    gemm_out<<<dim3(NT / 128, 1, 1), 256>>>(Wo, bo, out);
}

// round 5
// speedup vs baseline: 8.8333x; 1.1174x over previous
#include <cuda_runtime.h>
#include <cuda_fp16.h>
#include <cstdint>

#define NT 6144
#define KIN 256
#define DM 128
#define NH 4
#define HD 32
#define NSLICE 3
#define SLICE_KEYS (NT / NSLICE)   // 2048
#define BM 64
#define BN 64
#define NKT (SLICE_KEYS / BN)      // 32 key tiles per block

#define C1F 0.25502050681732154f   // (1/sqrt(32)) * log2(e)

// Scratch (device globals: allocation-free rule)
__device__ __half g_xh[NT * KIN];
__device__ __half g_wht[3 * KIN * DM];      // transposed [w][n][k], Wq pre-scaled by C1F
__device__ __half g_qh[NT * DM];
__device__ __half g_kh[NT * DM];
__device__ __half g_vh[NT * DM];
__device__ float g_attp[NSLICE][NT * DM];   // per-slice partial sum(p*v)
__device__ float g_lp[NSLICE][NT * NH];     // per-slice partial sum(p)

// ---------------------------------------------------------------------------
// PTX helpers
// ---------------------------------------------------------------------------
__device__ __forceinline__ uint32_t pack_f16x2(float lo, float hi) {
    uint32_t r; asm("cvt.rn.f16x2.f32 %0, %1, %2;" : "=r"(r) : "f"(hi), "f"(lo)); return r;
}
__device__ __forceinline__ uint32_t ex2_h2(uint32_t a) {
    uint32_t r; asm("ex2.approx.f16x2 %0, %1;" : "=r"(r) : "r"(a)); return r;
}
__device__ __forceinline__ void mma_f16(float d[4], uint32_t a0, uint32_t a1, uint32_t a2, uint32_t a3,
                                        uint32_t b0, uint32_t b1) {
    asm volatile(
        "mma.sync.aligned.m16n8k16.row.col.f32.f16.f16.f32 "
        "{%0,%1,%2,%3}, {%4,%5,%6,%7}, {%8,%9}, {%0,%1,%2,%3};\n"
        : "+f"(d[0]), "+f"(d[1]), "+f"(d[2]), "+f"(d[3])
        : "r"(a0), "r"(a1), "r"(a2), "r"(a3), "r"(b0), "r"(b1));
}
__device__ __forceinline__ void ldsm4(uint32_t r[4], uint32_t addr) {
    asm volatile("ldmatrix.sync.aligned.m8n8.x4.shared.b16 {%0,%1,%2,%3}, [%4];\n"
                 : "=r"(r[0]), "=r"(r[1]), "=r"(r[2]), "=r"(r[3]) : "r"(addr));
}
__device__ __forceinline__ void ldsm4t(uint32_t r[4], uint32_t addr) {
    asm volatile("ldmatrix.sync.aligned.m8n8.x4.trans.shared.b16 {%0,%1,%2,%3}, [%4];\n"
                 : "=r"(r[0]), "=r"(r[1]), "=r"(r[2]), "=r"(r[3]) : "r"(addr));
}
__device__ __forceinline__ void cpa16(uint32_t saddr, const void* gaddr) {
    asm volatile("cp.async.cg.shared.global [%0], [%1], 16;\n" :: "r"(saddr), "l"(gaddr));
}
__device__ __forceinline__ void cpa_commit() { asm volatile("cp.async.commit_group;\n" ::); }
__device__ __forceinline__ void cpa_wait1()  { asm volatile("cp.async.wait_group 1;\n" ::); }

// swizzled byte offset of 16B chunk (row, c) within a [rows][32 half] tile
#define SOFF(r, c) ((uint32_t)((((r) << 2) + ((c) ^ (((r) >> 1) & 3))) << 4))

// ---------------------------------------------------------------------------
// Conversion kernel: x -> fp16 (g_xh); W -> fp16 transposed [n][k] (g_wht).
// Wq (and bq, later in gemm epilogue) folded with C1F = scale*log2e.
// ---------------------------------------------------------------------------
__global__ __launch_bounds__(256) void convert_kernel(
    const float* __restrict__ x,
    const float* __restrict__ Wq, const float* __restrict__ Wk, const float* __restrict__ Wv)
{
    const int b = blockIdx.x, tid = threadIdx.x;
    if (b < 1536) {
        int base = b * 1024 + tid * 4;
        float4 v = *(const float4*)&x[base];
        *(__half2*)&g_xh[base]     = __floats2half2_rn(v.x, v.y);
        *(__half2*)&g_xh[base + 2] = __floats2half2_rn(v.z, v.w);
    } else {
        int bb = b - 1536;              // 0..47
        int w = bb >> 4, part = bb & 15;
        const float* W = (w == 0) ? Wq : (w == 1) ? Wk : Wv;
        float scale = (w == 0) ? C1F : 1.0f;
        __half* dst = g_wht + (size_t)w * (KIN * DM);
#pragma unroll
        for (int i = tid; i < 16 * DM; i += 256) {
            int k = part * 16 + (i >> 7);
            int n = i & 127;
            dst[n * KIN + k] = __float2half(W[k * DM + n] * scale);
        }
    }
}

// ---------------------------------------------------------------------------
// QKV projection GEMM (fp16 tensor cores): C = x @ W + b, output fp16.
// ---------------------------------------------------------------------------
__global__ __launch_bounds__(256, 2) void gemm_qkv_tc(
    const float* __restrict__ bq, const float* __restrict__ bk, const float* __restrict__ bv)
{
    __shared__ __align__(16) __half Xs[2][128 * 32];
    __shared__ __align__(16) __half Ws[2][128 * 32];

    const int tid = threadIdx.x, lane = tid & 31, w = tid >> 5;
    const int y = blockIdx.y;
    const int m0 = blockIdx.x * 128;
    const __half* wht = g_wht + (size_t)y * (KIN * DM);
    const float* bias = (y == 0) ? bq : (y == 1) ? bk : bv;
    const float bscale = (y == 0) ? C1F : 1.0f;
    __half* C = (y == 0) ? g_qh : (y == 1) ? g_kh : g_vh;

    const int lg = lane >> 3, lr = lane & 7;
    const int mg = lane >> 2, mt = lane & 3;

    const uint32_t xs0 = (uint32_t)__cvta_generic_to_shared(Xs);
    const uint32_t ws0 = (uint32_t)__cvta_generic_to_shared(Ws);
    const uint32_t BUF = 128 * 32 * 2;

#pragma unroll
    for (int s = 0; s < 2; ++s) {
#pragma unroll
        for (int r = 0; r < 2; ++r) {
            int id = tid + r * 256;
            int row = id >> 2, c = id & 3;
            cpa16(xs0 + s * BUF + SOFF(row, c), &g_xh[(size_t)(m0 + row) * KIN + s * 32 + c * 8]);
            cpa16(ws0 + s * BUF + SOFF(row, c), &wht[(size_t)row * KIN + s * 32 + c * 8]);
        }
        cpa_commit();
    }

    float Cf[16][4];
#pragma unroll
    for (int f = 0; f < 16; ++f)
#pragma unroll
        for (int r = 0; r < 4; ++r) Cf[f][r] = 0.f;

    uint32_t offA[2], offB[8][2];
#pragma unroll
    for (int kk = 0; kk < 2; ++kk)
        offA[kk] = SOFF(w * 16 + ((lg & 1) << 3) + lr, 2 * kk + (lg >> 1));
#pragma unroll
    for (int g = 0; g < 8; ++g)
#pragma unroll
        for (int kk = 0; kk < 2; ++kk)
            offB[g][kk] = SOFF(g * 16 + ((lg >> 1) << 3) + lr, 2 * kk + (lg & 1));

    for (int s = 0; s < 8; ++s) {
        cpa_wait1();
        __syncthreads();
        const uint32_t xb = xs0 + (uint32_t)(s & 1) * BUF;
        const uint32_t wb = ws0 + (uint32_t)(s & 1) * BUF;
#pragma unroll
        for (int kk = 0; kk < 2; ++kk) {
            uint32_t af[4];
            ldsm4(af, xb + offA[kk]);
#pragma unroll
            for (int g = 0; g < 8; ++g) {
                uint32_t bf[4];
                ldsm4(bf, wb + offB[g][kk]);
                mma_f16(Cf[2 * g],     af[0], af[1], af[2], af[3], bf[0], bf[1]);
                mma_f16(Cf[2 * g + 1], af[0], af[1], af[2], af[3], bf[2], bf[3]);
            }
        }
        __syncthreads();
        if (s + 2 < 8) {
            int k0 = (s + 2) * 32;
#pragma unroll
            for (int r = 0; r < 2; ++r) {
                int id = tid + r * 256;
                int row = id >> 2, c = id & 3;
                cpa16(xb + SOFF(row, c), &g_xh[(size_t)(m0 + row) * KIN + k0 + c * 8]);
                cpa16(wb + SOFF(row, c), &wht[(size_t)row * KIN + k0 + c * 8]);
            }
        }
        cpa_commit();
    }

    const int mr0 = m0 + w * 16 + mg;
    const int mr1 = mr0 + 8;
#pragma unroll
    for (int g = 0; g < 8; ++g)
#pragma unroll
        for (int s2 = 0; s2 < 2; ++s2) {
            int n = g * 16 + s2 * 8 + 2 * mt;
            float b0 = bias[n] * bscale, b1 = bias[n + 1] * bscale;
            float* d = Cf[2 * g + s2];
            *(__half2*)&C[(size_t)mr0 * DM + n] = __floats2half2_rn(d[0] + b0, d[1] + b1);
            *(__half2*)&C[(size_t)mr1 * DM + n] = __floats2half2_rn(d[2] + b0, d[3] + b1);
        }
}

// ---------------------------------------------------------------------------
// Fused attention: fp16 tensor-core flash attention (no-max softmax, split-K).
// ---------------------------------------------------------------------------
__global__ __launch_bounds__(128, 4) void attn_kernel(const float* __restrict__ dist_w)
{
    __shared__ __align__(16) __half Qs[BM * HD];
    __shared__ __align__(16) __half Ks[2][BN * HD];
    __shared__ __align__(16) __half Vs[2][BN * HD];

    const int tid   = threadIdx.x;
    const int lane  = tid & 31;
    const int w     = tid >> 5;
    const int h     = blockIdx.y;
    const int sl    = blockIdx.z;
    const int qbase = blockIdx.x * BM;
    const int jbase = sl * SLICE_KEYS;

    const int mg = lane >> 2, mt = lane & 3;
    const int lg = lane >> 3, lr = lane & 7;

    const uint32_t qs0 = (uint32_t)__cvta_generic_to_shared(Qs);
    const uint32_t ks0 = (uint32_t)__cvta_generic_to_shared(Ks);
    const uint32_t vs0 = (uint32_t)__cvta_generic_to_shared(Vs);
    const uint32_t KVB = BN * HD * 2;

    const float nC2 = -dist_w[h] * 1.44269504088896340f;

    uint32_t offK[4][2], offV[4][2], offQ[2];
#pragma unroll
    for (int p = 0; p < 4; ++p)
#pragma unroll
        for (int kk = 0; kk < 2; ++kk) {
            int rowk = 16 * p + ((lg >> 1) << 3) + lr;
            offK[p][kk] = SOFF(rowk, 2 * kk + (lg & 1));
            int rowv = 16 * p + ((lg & 1) << 3) + lr;
            offV[p][kk] = SOFF(rowv, 2 * kk + (lg >> 1));
        }
#pragma unroll
    for (int kk = 0; kk < 2; ++kk) {
        int rowq = w * 16 + ((lg & 1) << 3) + lr;
        offQ[kk] = SOFF(rowq, 2 * kk + (lg >> 1));
    }

    {
        const int id0 = tid, id1 = tid + 128;
        const int r0 = id0 >> 2, c0 = id0 & 3, r1 = id1 >> 2, c1 = id1 & 3;
        cpa16(qs0 + SOFF(r0, c0), &g_qh[(size_t)(qbase + r0) * DM + h * HD + c0 * 8]);
        cpa16(qs0 + SOFF(r1, c1), &g_qh[(size_t)(qbase + r1) * DM + h * HD + c1 * 8]);
        cpa16(ks0 + SOFF(r0, c0), &g_kh[(size_t)(jbase + r0) * DM + h * HD + c0 * 8]);
        cpa16(ks0 + SOFF(r1, c1), &g_kh[(size_t)(jbase + r1) * DM + h * HD + c1 * 8]);
        cpa16(vs0 + SOFF(r0, c0), &g_vh[(size_t)(jbase + r0) * DM + h * HD + c0 * 8]);
        cpa16(vs0 + SOFF(r1, c1), &g_vh[(size_t)(jbase + r1) * DM + h * HD + c1 * 8]);
        cpa_commit();
        const int jb1 = jbase + BN;
        cpa16(ks0 + KVB + SOFF(r0, c0), &g_kh[(size_t)(jb1 + r0) * DM + h * HD + c0 * 8]);
        cpa16(ks0 + KVB + SOFF(r1, c1), &g_kh[(size_t)(jb1 + r1) * DM + h * HD + c1 * 8]);
        cpa16(vs0 + KVB + SOFF(r0, c0), &g_vh[(size_t)(jb1 + r0) * DM + h * HD + c0 * 8]);
        cpa16(vs0 + KVB + SOFF(r1, c1), &g_vh[(size_t)(jb1 + r1) * DM + h * HD + c1 * 8]);
        cpa_commit();
    }
    cpa_wait1();
    __syncthreads();

    uint32_t qf[2][4];
#pragma unroll
    for (int kk = 0; kk < 2; ++kk) ldsm4(qf[kk], qs0 + offQ[kk]);

    float O[4][4];
#pragma unroll
    for (int n = 0; n < 4; ++n)
#pragma unroll
        for (int r = 0; r < 4; ++r) O[n][r] = 0.f;
    float lC[4] = {0.f, 0.f, 0.f, 0.f};
    const uint32_t ONE2 = 0x3C003C00u;

    const float ai0   = (float)(qbase + w * 16 + mg) * 0.01f;
    const float dbase = ai0 - (float)(jbase + 2 * mt) * 0.01f;

    for (int t = 0; t < NKT; ++t) {
        const uint32_t kb = ks0 + (uint32_t)(t & 1) * KVB;
        const uint32_t vb = vs0 + (uint32_t)(t & 1) * KVB;

        float S[8][4];
#pragma unroll
        for (int c = 0; c < 8; ++c)
#pragma unroll
            for (int r = 0; r < 4; ++r) S[c][r] = 0.f;

        uint32_t kf[4][2][4];
#pragma unroll
        for (int p = 0; p < 4; ++p)
#pragma unroll
            for (int kk = 0; kk < 2; ++kk) ldsm4(kf[p][kk], kb + offK[p][kk]);
#pragma unroll
        for (int p = 0; p < 4; ++p)
#pragma unroll
            for (int s2 = 0; s2 < 2; ++s2)
#pragma unroll
                for (int kk = 0; kk < 2; ++kk)
                    mma_f16(S[2 * p + s2], qf[kk][0], qf[kk][1], qf[kk][2], qf[kk][3],
                            kf[p][kk][2 * s2], kf[p][kk][2 * s2 + 1]);

        uint32_t pp[8][2];
        const float dt = dbase - (float)t * 0.64f;
#pragma unroll
        for (int c = 0; c < 8; ++c) {
            float d00 = dt - 0.08f * (float)c;
            float d01 = d00 - 0.01f;
            float d10 = d00 + 0.08f;
            float d11 = d00 + 0.07f;
            float a00 = fmaf(nC2, fabsf(d00), S[c][0]);
            float a01 = fmaf(nC2, fabsf(d01), S[c][1]);
            float a10 = fmaf(nC2, fabsf(d10), S[c][2]);
            float a11 = fmaf(nC2, fabsf(d11), S[c][3]);
            pp[c][0] = ex2_h2(pack_f16x2(a00, a01));
            pp[c][1] = ex2_h2(pack_f16x2(a10, a11));
        }

#pragma unroll
        for (int kc = 0; kc < 4; ++kc)
            mma_f16(lC, pp[2 * kc][0], pp[2 * kc][1], pp[2 * kc + 1][0], pp[2 * kc + 1][1],
                    ONE2, ONE2);

        uint32_t vf[4][2][4];
#pragma unroll
        for (int kc = 0; kc < 4; ++kc)
#pragma unroll
            for (int dp = 0; dp < 2; ++dp) ldsm4t(vf[kc][dp], vb + offV[kc][dp]);
#pragma unroll
        for (int kc = 0; kc < 4; ++kc)
#pragma unroll
            for (int nt = 0; nt < 4; ++nt)
                mma_f16(O[nt], pp[2 * kc][0], pp[2 * kc][1], pp[2 * kc + 1][0], pp[2 * kc + 1][1],
                        vf[kc][nt >> 1][2 * (nt & 1)], vf[kc][nt >> 1][2 * (nt & 1) + 1]);

        __syncthreads();

        if (t + 2 < NKT) {
            const int jb2 = jbase + (t + 2) * BN;
            const uint32_t kb2 = ks0 + (uint32_t)(t & 1) * KVB;
            const uint32_t vb2 = vs0 + (uint32_t)(t & 1) * KVB;
            const int id0 = tid, id1 = tid + 128;
            const int r0 = id0 >> 2, c0 = id0 & 3, r1 = id1 >> 2, c1 = id1 & 3;
            cpa16(kb2 + SOFF(r0, c0), &g_kh[(size_t)(jb2 + r0) * DM + h * HD + c0 * 8]);
            cpa16(kb2 + SOFF(r1, c1), &g_kh[(size_t)(jb2 + r1) * DM + h * HD + c1 * 8]);
            cpa16(vb2 + SOFF(r0, c0), &g_vh[(size_t)(jb2 + r0) * DM + h * HD + c0 * 8]);
            cpa16(vb2 + SOFF(r1, c1), &g_vh[(size_t)(jb2 + r1) * DM + h * HD + c1 * 8]);
        }
        cpa_commit();
        if (t < NKT - 1) {
            cpa_wait1();
            __syncthreads();
        }
    }

    const int i0 = qbase + w * 16 + mg;
    const int i1 = i0 + 8;
    if (mt == 0) {
        g_lp[sl][i0 * NH + h] = lC[0];
        g_lp[sl][i1 * NH + h] = lC[2];
    }
    float* oB = &g_attp[sl][0];
#pragma unroll
    for (int nt = 0; nt < 4; ++nt) {
        int d = nt * 8 + 2 * mt;
        *(float2*)&oB[(size_t)i0 * DM + h * HD + d] = make_float2(O[nt][0], O[nt][1]);
        *(float2*)&oB[(size_t)i1 * DM + h * HD + d] = make_float2(O[nt][2], O[nt][3]);
    }
}

// ---------------------------------------------------------------------------
// Output projection: out = (sum_s attp / sum_s l) @ Wo + bo   (fp32)
// BM=32, BK=32 -> grid 192 (full-chip), 256 threads, 4x4 micro-tile.
// ---------------------------------------------------------------------------
__global__ __launch_bounds__(256) void gemm_out(
    const float* __restrict__ B, const float* __restrict__ bias, float* __restrict__ out)
{
    __shared__ float As[32][33];
    __shared__ float Bs[32][128];

    const int tid = threadIdx.x;
    const int m0  = blockIdx.x * 32;
    const int tx  = tid & 31;        // 4 output cols each
    const int ty  = tid >> 5;        // 4 output rows each

    float acc[4][4];
#pragma unroll
    for (int i = 0; i < 4; ++i)
#pragma unroll
        for (int j = 0; j < 4; ++j) acc[i][j] = 0.f;

#pragma unroll
    for (int k0 = 0; k0 < DM; k0 += 32) {
        // ---- A tile (32 x 32): slice-combine + normalize; 1 float4 slot/thread
        {
            int m  = tid >> 3;               // 0..31
            int cq = (tid & 7) << 2;         // 0,4,...,28
            int row = m0 + m;
            int kk  = k0 + cq;
            int hh  = k0 >> 5;               // same head for whole BK tile
            float4 av = make_float4(0.f, 0.f, 0.f, 0.f);
            float lsum = 0.f;
#pragma unroll
            for (int s = 0; s < NSLICE; ++s) {
                float4 tv = *(const float4*)&g_attp[s][(size_t)row * DM + kk];
                av.x += tv.x; av.y += tv.y; av.z += tv.z; av.w += tv.w;
                lsum += g_lp[s][row * NH + hh];
            }
            float inv = 1.0f / lsum;
            As[cq + 0][m] = av.x * inv; As[cq + 1][m] = av.y * inv;
            As[cq + 2][m] = av.z * inv; As[cq + 3][m] = av.w * inv;
        }
        // ---- B tile (32 x 128): 4 float4 slots/thread
#pragma unroll
        for (int r = 0; r < 4; ++r) {
            int slot = tid + r * 256;
            int kr = slot >> 5;
            int nq = (slot & 31) << 2;
            *(float4*)&Bs[kr][nq] = *(const float4*)&B[(size_t)(k0 + kr) * 128 + nq];
        }
        __syncthreads();
#pragma unroll
        for (int kk = 0; kk < 32; ++kk) {
            float a[4], b[4];
#pragma unroll
            for (int i = 0; i < 4; ++i) a[i] = As[kk][ty * 4 + i];
#pragma unroll
            for (int j = 0; j < 4; ++j) b[j] = Bs[kk][tx * 4 + j];
#pragma unroll
            for (int i = 0; i < 4; ++i)
#pragma unroll
                for (int j = 0; j < 4; ++j) acc[i][j] = fmaf(a[i], b[j], acc[i][j]);
        }
        __syncthreads();
    }

#pragma unroll
    for (int i = 0; i < 4; ++i) {
        int m = m0 + ty * 4 + i;
        int n = tx * 4;
        float4 o;
        o.x = acc[i][0] + bias[n + 0];
        o.y = acc[i][1] + bias[n + 1];
        o.z = acc[i][2] + bias[n + 2];
        o.w = acc[i][3] + bias[n + 3];
        *(float4*)&out[(size_t)m * 128 + n] = o;
    }
}

// ---------------------------------------------------------------------------
extern "C" void kernel_launch(void* const* d_in, const int* in_sizes, int n_in,
                              void* d_out, int out_size)
{
    const float* x  = (const float*)d_in[0];
    const float* Wq = (const float*)d_in[1];
    const float* bq = (const float*)d_in[2];
    const float* Wk = (const float*)d_in[3];
    const float* bk = (const float*)d_in[4];
    const float* Wv = (const float*)d_in[5];
    const float* bv = (const float*)d_in[6];
    const float* Wo = (const float*)d_in[7];
    const float* bo = (const float*)d_in[8];
    const float* dw = (const float*)d_in[9];
    float* out = (float*)d_out;

    convert_kernel<<<1584, 256>>>(x, Wq, Wk, Wv);
    gemm_qkv_tc<<<dim3(NT / 128, 3, 1), 256>>>(bq, bk, bv);
    attn_kernel<<<dim3(NT / BM, NH, NSLICE), 128>>>(dw);
    gemm_out<<<dim3(NT / 32, 1, 1), 256>>>(Wo, bo, out);
}

// round 6
// speedup vs baseline: 9.4618x; 1.0712x over previous
#include <cuda_runtime.h>
#include <cuda_fp16.h>
#include <cstdint>

#define NT 6144
#define KIN 256
#define DM 128
#define NH 4
#define HD 32
#define NSLICE 3
#define SLICE_KEYS (NT / NSLICE)   // 2048
#define BM 64
#define BN 64
#define NKT (SLICE_KEYS / BN)      // 32 key tiles per block

#define C1F 0.25502050681732154f   // (1/sqrt(32)) * log2(e)

// Scratch (device globals: allocation-free rule)
__device__ __half g_xh[NT * KIN];
__device__ __half g_wht[3 * KIN * DM];      // transposed [w][n][k], Wq pre-scaled by C1F
__device__ __half g_woht[DM * DM];          // Wo transposed [n][k]
__device__ __half g_qh[NT * DM];
__device__ __half g_kh[NT * DM];
__device__ __half g_vh[NT * DM];
__device__ __half g_ah[NT * DM];            // combined+normalized attention output (fp16)
__device__ float g_attp[NSLICE][NT * DM];   // per-slice partial sum(p*v)
__device__ float g_lp[NSLICE][NT * NH];     // per-slice partial sum(p)

// ---------------------------------------------------------------------------
// PTX helpers
// ---------------------------------------------------------------------------
__device__ __forceinline__ uint32_t pack_f16x2(float lo, float hi) {
    uint32_t r; asm("cvt.rn.f16x2.f32 %0, %1, %2;" : "=r"(r) : "f"(hi), "f"(lo)); return r;
}
__device__ __forceinline__ uint32_t ex2_h2(uint32_t a) {
    uint32_t r; asm("ex2.approx.f16x2 %0, %1;" : "=r"(r) : "r"(a)); return r;
}
__device__ __forceinline__ void mma_f16(float d[4], uint32_t a0, uint32_t a1, uint32_t a2, uint32_t a3,
                                        uint32_t b0, uint32_t b1) {
    asm volatile(
        "mma.sync.aligned.m16n8k16.row.col.f32.f16.f16.f32 "
        "{%0,%1,%2,%3}, {%4,%5,%6,%7}, {%8,%9}, {%0,%1,%2,%3};\n"
        : "+f"(d[0]), "+f"(d[1]), "+f"(d[2]), "+f"(d[3])
        : "r"(a0), "r"(a1), "r"(a2), "r"(a3), "r"(b0), "r"(b1));
}
__device__ __forceinline__ void ldsm4(uint32_t r[4], uint32_t addr) {
    asm volatile("ldmatrix.sync.aligned.m8n8.x4.shared.b16 {%0,%1,%2,%3}, [%4];\n"
                 : "=r"(r[0]), "=r"(r[1]), "=r"(r[2]), "=r"(r[3]) : "r"(addr));
}
__device__ __forceinline__ void ldsm4t(uint32_t r[4], uint32_t addr) {
    asm volatile("ldmatrix.sync.aligned.m8n8.x4.trans.shared.b16 {%0,%1,%2,%3}, [%4];\n"
                 : "=r"(r[0]), "=r"(r[1]), "=r"(r[2]), "=r"(r[3]) : "r"(addr));
}
__device__ __forceinline__ void cpa16(uint32_t saddr, const void* gaddr) {
    asm volatile("cp.async.cg.shared.global [%0], [%1], 16;\n" :: "r"(saddr), "l"(gaddr));
}
__device__ __forceinline__ void cpa_commit() { asm volatile("cp.async.commit_group;\n" ::); }
__device__ __forceinline__ void cpa_wait1()  { asm volatile("cp.async.wait_group 1;\n" ::); }

// swizzled byte offset of 16B chunk (row, c) within a [rows][32 half] tile
#define SOFF(r, c) ((uint32_t)((((r) << 2) + ((c) ^ (((r) >> 1) & 3))) << 4))

// ---------------------------------------------------------------------------
// Conversion kernel: x -> fp16; Wq/Wk/Wv -> fp16 transposed (Wq scaled by C1F);
// Wo -> fp16 transposed.
// ---------------------------------------------------------------------------
__global__ __launch_bounds__(256) void convert_kernel(
    const float* __restrict__ x,
    const float* __restrict__ Wq, const float* __restrict__ Wk, const float* __restrict__ Wv,
    const float* __restrict__ Wo)
{
    const int b = blockIdx.x, tid = threadIdx.x;
    if (b < 1536) {
        int base = b * 1024 + tid * 4;
        float4 v = *(const float4*)&x[base];
        *(__half2*)&g_xh[base]     = __floats2half2_rn(v.x, v.y);
        *(__half2*)&g_xh[base + 2] = __floats2half2_rn(v.z, v.w);
    } else if (b < 1584) {
        int bb = b - 1536;              // 0..47
        int w = bb >> 4, part = bb & 15;
        const float* W = (w == 0) ? Wq : (w == 1) ? Wk : Wv;
        float scale = (w == 0) ? C1F : 1.0f;
        __half* dst = g_wht + (size_t)w * (KIN * DM);
#pragma unroll
        for (int i = tid; i < 16 * DM; i += 256) {
            int k = part * 16 + (i >> 7);
            int n = i & 127;
            dst[n * KIN + k] = __float2half(W[k * DM + n] * scale);
        }
    } else {
        int bb = b - 1584;              // 0..15
#pragma unroll
        for (int i = tid; i < 8 * DM; i += 256) {
            int k = bb * 8 + (i >> 7);
            int n = i & 127;
            g_woht[n * DM + k] = __float2half(Wo[k * DM + n]);
        }
    }
}

// ---------------------------------------------------------------------------
// QKV projection GEMM (fp16 tensor cores): C = x @ W + b, output fp16.
// ---------------------------------------------------------------------------
__global__ __launch_bounds__(256, 2) void gemm_qkv_tc(
    const float* __restrict__ bq, const float* __restrict__ bk, const float* __restrict__ bv)
{
    __shared__ __align__(16) __half Xs[2][128 * 32];
    __shared__ __align__(16) __half Ws[2][128 * 32];

    const int tid = threadIdx.x, lane = tid & 31, w = tid >> 5;
    const int y = blockIdx.y;
    const int m0 = blockIdx.x * 128;
    const __half* wht = g_wht + (size_t)y * (KIN * DM);
    const float* bias = (y == 0) ? bq : (y == 1) ? bk : bv;
    const float bscale = (y == 0) ? C1F : 1.0f;
    __half* C = (y == 0) ? g_qh : (y == 1) ? g_kh : g_vh;

    const int lg = lane >> 3, lr = lane & 7;
    const int mg = lane >> 2, mt = lane & 3;

    const uint32_t xs0 = (uint32_t)__cvta_generic_to_shared(Xs);
    const uint32_t ws0 = (uint32_t)__cvta_generic_to_shared(Ws);
    const uint32_t BUF = 128 * 32 * 2;

#pragma unroll
    for (int s = 0; s < 2; ++s) {
#pragma unroll
        for (int r = 0; r < 2; ++r) {
            int id = tid + r * 256;
            int row = id >> 2, c = id & 3;
            cpa16(xs0 + s * BUF + SOFF(row, c), &g_xh[(size_t)(m0 + row) * KIN + s * 32 + c * 8]);
            cpa16(ws0 + s * BUF + SOFF(row, c), &wht[(size_t)row * KIN + s * 32 + c * 8]);
        }
        cpa_commit();
    }

    float Cf[16][4];
#pragma unroll
    for (int f = 0; f < 16; ++f)
#pragma unroll
        for (int r = 0; r < 4; ++r) Cf[f][r] = 0.f;

    uint32_t offA[2], offB[8][2];
#pragma unroll
    for (int kk = 0; kk < 2; ++kk)
        offA[kk] = SOFF(w * 16 + ((lg & 1) << 3) + lr, 2 * kk + (lg >> 1));
#pragma unroll
    for (int g = 0; g < 8; ++g)
#pragma unroll
        for (int kk = 0; kk < 2; ++kk)
            offB[g][kk] = SOFF(g * 16 + ((lg >> 1) << 3) + lr, 2 * kk + (lg & 1));

    for (int s = 0; s < 8; ++s) {
        cpa_wait1();
        __syncthreads();
        const uint32_t xb = xs0 + (uint32_t)(s & 1) * BUF;
        const uint32_t wb = ws0 + (uint32_t)(s & 1) * BUF;
#pragma unroll
        for (int kk = 0; kk < 2; ++kk) {
            uint32_t af[4];
            ldsm4(af, xb + offA[kk]);
#pragma unroll
            for (int g = 0; g < 8; ++g) {
                uint32_t bf[4];
                ldsm4(bf, wb + offB[g][kk]);
                mma_f16(Cf[2 * g],     af[0], af[1], af[2], af[3], bf[0], bf[1]);
                mma_f16(Cf[2 * g + 1], af[0], af[1], af[2], af[3], bf[2], bf[3]);
            }
        }
        __syncthreads();
        if (s + 2 < 8) {
            int k0 = (s + 2) * 32;
#pragma unroll
            for (int r = 0; r < 2; ++r) {
                int id = tid + r * 256;
                int row = id >> 2, c = id & 3;
                cpa16(xb + SOFF(row, c), &g_xh[(size_t)(m0 + row) * KIN + k0 + c * 8]);
                cpa16(wb + SOFF(row, c), &wht[(size_t)row * KIN + k0 + c * 8]);
            }
        }
        cpa_commit();
    }

    const int mr0 = m0 + w * 16 + mg;
    const int mr1 = mr0 + 8;
#pragma unroll
    for (int g = 0; g < 8; ++g)
#pragma unroll
        for (int s2 = 0; s2 < 2; ++s2) {
            int n = g * 16 + s2 * 8 + 2 * mt;
            float b0 = bias[n] * bscale, b1 = bias[n + 1] * bscale;
            float* d = Cf[2 * g + s2];
            *(__half2*)&C[(size_t)mr0 * DM + n] = __floats2half2_rn(d[0] + b0, d[1] + b1);
            *(__half2*)&C[(size_t)mr1 * DM + n] = __floats2half2_rn(d[2] + b0, d[3] + b1);
        }
}

// ---------------------------------------------------------------------------
// Fused attention: fp16 tensor-core flash attention (no-max softmax, split-K).
// ---------------------------------------------------------------------------
__global__ __launch_bounds__(128, 4) void attn_kernel(const float* __restrict__ dist_w)
{
    __shared__ __align__(16) __half Qs[BM * HD];
    __shared__ __align__(16) __half Ks[2][BN * HD];
    __shared__ __align__(16) __half Vs[2][BN * HD];

    const int tid   = threadIdx.x;
    const int lane  = tid & 31;
    const int w     = tid >> 5;
    const int h     = blockIdx.y;
    const int sl    = blockIdx.z;
    const int qbase = blockIdx.x * BM;
    const int jbase = sl * SLICE_KEYS;

    const int mg = lane >> 2, mt = lane & 3;
    const int lg = lane >> 3, lr = lane & 7;

    const uint32_t qs0 = (uint32_t)__cvta_generic_to_shared(Qs);
    const uint32_t ks0 = (uint32_t)__cvta_generic_to_shared(Ks);
    const uint32_t vs0 = (uint32_t)__cvta_generic_to_shared(Vs);
    const uint32_t KVB = BN * HD * 2;

    const float nC2 = -dist_w[h] * 1.44269504088896340f;

    uint32_t offK[4][2], offV[4][2], offQ[2];
#pragma unroll
    for (int p = 0; p < 4; ++p)
#pragma unroll
        for (int kk = 0; kk < 2; ++kk) {
            int rowk = 16 * p + ((lg >> 1) << 3) + lr;
            offK[p][kk] = SOFF(rowk, 2 * kk + (lg & 1));
            int rowv = 16 * p + ((lg & 1) << 3) + lr;
            offV[p][kk] = SOFF(rowv, 2 * kk + (lg >> 1));
        }
#pragma unroll
    for (int kk = 0; kk < 2; ++kk) {
        int rowq = w * 16 + ((lg & 1) << 3) + lr;
        offQ[kk] = SOFF(rowq, 2 * kk + (lg >> 1));
    }

    {
        const int id0 = tid, id1 = tid + 128;
        const int r0 = id0 >> 2, c0 = id0 & 3, r1 = id1 >> 2, c1 = id1 & 3;
        cpa16(qs0 + SOFF(r0, c0), &g_qh[(size_t)(qbase + r0) * DM + h * HD + c0 * 8]);
        cpa16(qs0 + SOFF(r1, c1), &g_qh[(size_t)(qbase + r1) * DM + h * HD + c1 * 8]);
        cpa16(ks0 + SOFF(r0, c0), &g_kh[(size_t)(jbase + r0) * DM + h * HD + c0 * 8]);
        cpa16(ks0 + SOFF(r1, c1), &g_kh[(size_t)(jbase + r1) * DM + h * HD + c1 * 8]);
        cpa16(vs0 + SOFF(r0, c0), &g_vh[(size_t)(jbase + r0) * DM + h * HD + c0 * 8]);
        cpa16(vs0 + SOFF(r1, c1), &g_vh[(size_t)(jbase + r1) * DM + h * HD + c1 * 8]);
        cpa_commit();
        const int jb1 = jbase + BN;
        cpa16(ks0 + KVB + SOFF(r0, c0), &g_kh[(size_t)(jb1 + r0) * DM + h * HD + c0 * 8]);
        cpa16(ks0 + KVB + SOFF(r1, c1), &g_kh[(size_t)(jb1 + r1) * DM + h * HD + c1 * 8]);
        cpa16(vs0 + KVB + SOFF(r0, c0), &g_vh[(size_t)(jb1 + r0) * DM + h * HD + c0 * 8]);
        cpa16(vs0 + KVB + SOFF(r1, c1), &g_vh[(size_t)(jb1 + r1) * DM + h * HD + c1 * 8]);
        cpa_commit();
    }
    cpa_wait1();
    __syncthreads();

    uint32_t qf[2][4];
#pragma unroll
    for (int kk = 0; kk < 2; ++kk) ldsm4(qf[kk], qs0 + offQ[kk]);

    float O[4][4];
#pragma unroll
    for (int n = 0; n < 4; ++n)
#pragma unroll
        for (int r = 0; r < 4; ++r) O[n][r] = 0.f;
    float lC[4] = {0.f, 0.f, 0.f, 0.f};
    const uint32_t ONE2 = 0x3C003C00u;

    const float ai0   = (float)(qbase + w * 16 + mg) * 0.01f;
    const float dbase = ai0 - (float)(jbase + 2 * mt) * 0.01f;

    for (int t = 0; t < NKT; ++t) {
        const uint32_t kb = ks0 + (uint32_t)(t & 1) * KVB;
        const uint32_t vb = vs0 + (uint32_t)(t & 1) * KVB;

        float S[8][4];
#pragma unroll
        for (int c = 0; c < 8; ++c)
#pragma unroll
            for (int r = 0; r < 4; ++r) S[c][r] = 0.f;

        uint32_t kf[4][2][4];
#pragma unroll
        for (int p = 0; p < 4; ++p)
#pragma unroll
            for (int kk = 0; kk < 2; ++kk) ldsm4(kf[p][kk], kb + offK[p][kk]);
#pragma unroll
        for (int p = 0; p < 4; ++p)
#pragma unroll
            for (int s2 = 0; s2 < 2; ++s2)
#pragma unroll
                for (int kk = 0; kk < 2; ++kk)
                    mma_f16(S[2 * p + s2], qf[kk][0], qf[kk][1], qf[kk][2], qf[kk][3],
                            kf[p][kk][2 * s2], kf[p][kk][2 * s2 + 1]);

        uint32_t pp[8][2];
        const float dt = dbase - (float)t * 0.64f;
#pragma unroll
        for (int c = 0; c < 8; ++c) {
            float d00 = dt - 0.08f * (float)c;
            float d01 = d00 - 0.01f;
            float d10 = d00 + 0.08f;
            float d11 = d00 + 0.07f;
            float a00 = fmaf(nC2, fabsf(d00), S[c][0]);
            float a01 = fmaf(nC2, fabsf(d01), S[c][1]);
            float a10 = fmaf(nC2, fabsf(d10), S[c][2]);
            float a11 = fmaf(nC2, fabsf(d11), S[c][3]);
            pp[c][0] = ex2_h2(pack_f16x2(a00, a01));
            pp[c][1] = ex2_h2(pack_f16x2(a10, a11));
        }

#pragma unroll
        for (int kc = 0; kc < 4; ++kc)
            mma_f16(lC, pp[2 * kc][0], pp[2 * kc][1], pp[2 * kc + 1][0], pp[2 * kc + 1][1],
                    ONE2, ONE2);

        uint32_t vf[4][2][4];
#pragma unroll
        for (int kc = 0; kc < 4; ++kc)
#pragma unroll
            for (int dp = 0; dp < 2; ++dp) ldsm4t(vf[kc][dp], vb + offV[kc][dp]);
#pragma unroll
        for (int kc = 0; kc < 4; ++kc)
#pragma unroll
            for (int nt = 0; nt < 4; ++nt)
                mma_f16(O[nt], pp[2 * kc][0], pp[2 * kc][1], pp[2 * kc + 1][0], pp[2 * kc + 1][1],
                        vf[kc][nt >> 1][2 * (nt & 1)], vf[kc][nt >> 1][2 * (nt & 1) + 1]);

        __syncthreads();

        if (t + 2 < NKT) {
            const int jb2 = jbase + (t + 2) * BN;
            const uint32_t kb2 = ks0 + (uint32_t)(t & 1) * KVB;
            const uint32_t vb2 = vs0 + (uint32_t)(t & 1) * KVB;
            const int id0 = tid, id1 = tid + 128;
            const int r0 = id0 >> 2, c0 = id0 & 3, r1 = id1 >> 2, c1 = id1 & 3;
            cpa16(kb2 + SOFF(r0, c0), &g_kh[(size_t)(jb2 + r0) * DM + h * HD + c0 * 8]);
            cpa16(kb2 + SOFF(r1, c1), &g_kh[(size_t)(jb2 + r1) * DM + h * HD + c1 * 8]);
            cpa16(vb2 + SOFF(r0, c0), &g_vh[(size_t)(jb2 + r0) * DM + h * HD + c0 * 8]);
            cpa16(vb2 + SOFF(r1, c1), &g_vh[(size_t)(jb2 + r1) * DM + h * HD + c1 * 8]);
        }
        cpa_commit();
        if (t < NKT - 1) {
            cpa_wait1();
            __syncthreads();
        }
    }

    const int i0 = qbase + w * 16 + mg;
    const int i1 = i0 + 8;
    if (mt == 0) {
        g_lp[sl][i0 * NH + h] = lC[0];
        g_lp[sl][i1 * NH + h] = lC[2];
    }
    float* oB = &g_attp[sl][0];
#pragma unroll
    for (int nt = 0; nt < 4; ++nt) {
        int d = nt * 8 + 2 * mt;
        *(float2*)&oB[(size_t)i0 * DM + h * HD + d] = make_float2(O[nt][0], O[nt][1]);
        *(float2*)&oB[(size_t)i1 * DM + h * HD + d] = make_float2(O[nt][2], O[nt][3]);
    }
}

// ---------------------------------------------------------------------------
// Combine: g_ah[m][k] = fp16( (sum_s attp[s]) / (sum_s l[s]) ). Pure streaming.
// ---------------------------------------------------------------------------
__global__ __launch_bounds__(256) void combine_kernel()
{
    const int idx = blockIdx.x * 256 + threadIdx.x;   // 0 .. NT*32-1
    const int m  = idx >> 5;
    const int q  = idx & 31;
    const int kk = q << 2;
    const int hh = q >> 3;

    float4 av = make_float4(0.f, 0.f, 0.f, 0.f);
    float lsum = 0.f;
#pragma unroll
    for (int s = 0; s < NSLICE; ++s) {
        float4 tv = *(const float4*)&g_attp[s][(size_t)m * DM + kk];
        av.x += tv.x; av.y += tv.y; av.z += tv.z; av.w += tv.w;
        lsum += g_lp[s][m * NH + hh];
    }
    float inv = 1.0f / lsum;
    __half2 h0 = __floats2half2_rn(av.x * inv, av.y * inv);
    __half2 h1 = __floats2half2_rn(av.z * inv, av.w * inv);
    uint2 pk = make_uint2(*(uint32_t*)&h0, *(uint32_t*)&h1);
    *(uint2*)&g_ah[(size_t)m * DM + kk] = pk;
}

// ---------------------------------------------------------------------------
// Output projection (fp16 tensor cores): out = g_ah @ Wo + bo, fp32 output.
// BM=64, 128 threads (4 warps), grid 96. K=128 in 4 stages of 32.
// ---------------------------------------------------------------------------
__global__ __launch_bounds__(128, 4) void gemm_out_tc(
    const float* __restrict__ bo, float* __restrict__ out)
{
    __shared__ __align__(16) __half As[2][64 * 32];
    __shared__ __align__(16) __half Bs[2][128 * 32];

    const int tid = threadIdx.x, lane = tid & 31, w = tid >> 5;
    const int m0 = blockIdx.x * 64;

    const int lg = lane >> 3, lr = lane & 7;
    const int mg = lane >> 2, mt = lane & 3;

    const uint32_t as0 = (uint32_t)__cvta_generic_to_shared(As);
    const uint32_t bs0 = (uint32_t)__cvta_generic_to_shared(Bs);
    const uint32_t ABUF = 64 * 32 * 2;
    const uint32_t BBUF = 128 * 32 * 2;

#pragma unroll
    for (int s = 0; s < 2; ++s) {
#pragma unroll
        for (int r = 0; r < 2; ++r) {
            int id = tid + r * 128;
            int row = id >> 2, c = id & 3;
            cpa16(as0 + s * ABUF + SOFF(row, c), &g_ah[(size_t)(m0 + row) * DM + s * 32 + c * 8]);
        }
#pragma unroll
        for (int r = 0; r < 4; ++r) {
            int id = tid + r * 128;
            int row = id >> 2, c = id & 3;
            cpa16(bs0 + s * BBUF + SOFF(row, c), &g_woht[(size_t)row * DM + s * 32 + c * 8]);
        }
        cpa_commit();
    }

    float Cf[16][4];
#pragma unroll
    for (int f = 0; f < 16; ++f)
#pragma unroll
        for (int r = 0; r < 4; ++r) Cf[f][r] = 0.f;

    uint32_t offA[2], offB[8][2];
#pragma unroll
    for (int kk = 0; kk < 2; ++kk)
        offA[kk] = SOFF(w * 16 + ((lg & 1) << 3) + lr, 2 * kk + (lg >> 1));
#pragma unroll
    for (int g = 0; g < 8; ++g)
#pragma unroll
        for (int kk = 0; kk < 2; ++kk)
            offB[g][kk] = SOFF(g * 16 + ((lg >> 1) << 3) + lr, 2 * kk + (lg & 1));

    for (int s = 0; s < 4; ++s) {
        cpa_wait1();
        __syncthreads();
        const uint32_t ab = as0 + (uint32_t)(s & 1) * ABUF;
        const uint32_t bb = bs0 + (uint32_t)(s & 1) * BBUF;
#pragma unroll
        for (int kk = 0; kk < 2; ++kk) {
            uint32_t af[4];
            ldsm4(af, ab + offA[kk]);
#pragma unroll
            for (int g = 0; g < 8; ++g) {
                uint32_t bf[4];
                ldsm4(bf, bb + offB[g][kk]);
                mma_f16(Cf[2 * g],     af[0], af[1], af[2], af[3], bf[0], bf[1]);
                mma_f16(Cf[2 * g + 1], af[0], af[1], af[2], af[3], bf[2], bf[3]);
            }
        }
        __syncthreads();
        if (s + 2 < 4) {
            int k0 = (s + 2) * 32;
#pragma unroll
            for (int r = 0; r < 2; ++r) {
                int id = tid + r * 128;
                int row = id >> 2, c = id & 3;
                cpa16(ab + SOFF(row, c), &g_ah[(size_t)(m0 + row) * DM + k0 + c * 8]);
            }
#pragma unroll
            for (int r = 0; r < 4; ++r) {
                int id = tid + r * 128;
                int row = id >> 2, c = id & 3;
                cpa16(bb + SOFF(row, c), &g_woht[(size_t)row * DM + k0 + c * 8]);
            }
        }
        cpa_commit();
    }

    const int mr0 = m0 + w * 16 + mg;
    const int mr1 = mr0 + 8;
#pragma unroll
    for (int g = 0; g < 8; ++g)
#pragma unroll
        for (int s2 = 0; s2 < 2; ++s2) {
            int n = g * 16 + s2 * 8 + 2 * mt;
            float b0 = bo[n], b1 = bo[n + 1];
            float* d = Cf[2 * g + s2];
            *(float2*)&out[(size_t)mr0 * DM + n] = make_float2(d[0] + b0, d[1] + b1);
            *(float2*)&out[(size_t)mr1 * DM + n] = make_float2(d[2] + b0, d[3] + b1);
        }
}

// ---------------------------------------------------------------------------
extern "C" void kernel_launch(void* const* d_in, const int* in_sizes, int n_in,
                              void* d_out, int out_size)
{
    const float* x  = (const float*)d_in[0];
    const float* Wq = (const float*)d_in[1];
    const float* bq = (const float*)d_in[2];
    const float* Wk = (const float*)d_in[3];
    const float* bk = (const float*)d_in[4];
    const float* Wv = (const float*)d_in[5];
    const float* bv = (const float*)d_in[6];
    const float* Wo = (const float*)d_in[7];
    const float* bo = (const float*)d_in[8];
    const float* dw = (const float*)d_in[9];
    float* out = (float*)d_out;

    convert_kernel<<<1600, 256>>>(x, Wq, Wk, Wv, Wo);
    gemm_qkv_tc<<<dim3(NT / 128, 3, 1), 256>>>(bq, bk, bv);
    attn_kernel<<<dim3(NT / BM, NH, NSLICE), 128>>>(dw);
    combine_kernel<<<NT * 32 / 256, 256>>>();
    gemm_out_tc<<<NT / 64, 128>>>(bo, out);
}